// round 9
// baseline (speedup 1.0000x reference)
#include <cuda_runtime.h>
#include <cuda.h>
#include <cuda_fp16.h>

typedef unsigned int u32;
typedef unsigned long long u64;

#define BB 4
#define SS 2048
#define EE 1024
#define HH 16
#define DD 64
#define QQ 4
#define MM (BB*SS)     /* 8192 tokens */
#define NQKV 6144      /* 4096 q + 1024 k + 1024 v */

// ───────── scratch (allocation-free rule: __device__ globals) ─────────
__device__ float g_qkv[(size_t)MM * NQKV];      // fused projection output
__device__ float g_bqkv[NQKV];

__device__ __half g_xh[(size_t)MM*EE],  g_xl[(size_t)MM*EE];
__device__ __half g_zh[(size_t)MM*EE],  g_zl[(size_t)MM*EE];
__device__ __half g_wqkv[(size_t)NQKV*EE];      // concatenated Wq|Wk|Wv
__device__ __half g_wo[(size_t)EE*EE];

__device__ __forceinline__ u32 smem_u32(const void* p) {
    u32 a;
    asm("{ .reg .u64 t; cvta.to.shared.u64 t, %1; cvt.u32.u64 %0, t; }"
        : "=r"(a) : "l"(p));
    return a;
}
__device__ __forceinline__ void ldsm4(u32 addr, u32* r) {
    asm volatile("ldmatrix.sync.aligned.m8n8.x4.shared.b16 {%0,%1,%2,%3}, [%4];"
                 : "=r"(r[0]), "=r"(r[1]), "=r"(r[2]), "=r"(r[3]) : "r"(addr));
}
__device__ __forceinline__ void mma16816(float* c, const u32* a, const u32* b) {
    asm volatile(
        "mma.sync.aligned.m16n8k16.row.col.f32.f16.f16.f32 "
        "{%0,%1,%2,%3}, {%4,%5,%6,%7}, {%8,%9}, {%0,%1,%2,%3};"
        : "+f"(c[0]), "+f"(c[1]), "+f"(c[2]), "+f"(c[3])
        : "r"(a[0]), "r"(a[1]), "r"(a[2]), "r"(a[3]), "r"(b[0]), "r"(b[1]));
}
__device__ __forceinline__ void tma2d(u32 saddr, const CUtensorMap* m,
                                      int cx, int cy, u32 mbar) {
    asm volatile(
        "cp.async.bulk.tensor.2d.shared::cta.global.tile.mbarrier::complete_tx::bytes "
        "[%0], [%1, {%2, %3}], [%4];"
        :: "r"(saddr), "l"(m), "r"(cx), "r"(cy), "r"(mbar) : "memory");
}
#define MBAR_INIT(addr, cnt) \
    asm volatile("mbarrier.init.shared.b64 [%0], %1;" :: "r"(addr), "r"(cnt) : "memory")
#define MBAR_EXPECT(addr, bytes) \
    asm volatile("mbarrier.arrive.expect_tx.shared.b64 _, [%0], %1;" \
                 :: "r"(addr), "r"(bytes) : "memory")
__device__ __forceinline__ void mbar_wait(u32 addr, u32 parity) {
    asm volatile(
        "{\n\t.reg .pred P;\n\t"
        "W%=:\n\t"
        "mbarrier.try_wait.parity.acquire.cta.shared::cta.b64 P, [%0], %1, 0x989680;\n\t"
        "@P bra D%=;\n\t"
        "bra W%=;\n\t"
        "D%=:\n\t}"
        :: "r"(addr), "r"(parity) : "memory");
}
#define SWZ(off) ((u32)(off) ^ ((((u32)(off)) >> 3) & 0x70))

// ───────── fp32 → fp16 hi/lo split (activation side) ─────────
__global__ __launch_bounds__(256) void split16(
    const float* __restrict__ s, __half* __restrict__ h,
    __half* __restrict__ l, int n4)
{
    int i = blockIdx.x * blockDim.x + threadIdx.x;
    if (i >= n4) return;
    float4 v = ((const float4*)s)[i];
    float f[4] = {v.x, v.y, v.z, v.w};
    ushort4 ho, lo;
    unsigned short* hp = &ho.x; unsigned short* lp = &lo.x;
    #pragma unroll
    for (int j = 0; j < 4; j++) {
        __half hb = __float2half_rn(f[j]);
        __half lb = __float2half_rn(f[j] - __half2float(hb));
        hp[j] = __half_as_ushort(hb);
        lp[j] = __half_as_ushort(lb);
    }
    ((ushort4*)h)[i] = ho;
    ((ushort4*)l)[i] = lo;
}

// ───────── fp32 → fp16 (weight side, single) ─────────
__global__ __launch_bounds__(256) void conv16(
    const float* __restrict__ s, __half* __restrict__ h, int n4)
{
    int i = blockIdx.x * blockDim.x + threadIdx.x;
    if (i >= n4) return;
    float4 v = ((const float4*)s)[i];
    ushort4 ho;
    ho.x = __half_as_ushort(__float2half_rn(v.x));
    ho.y = __half_as_ushort(__float2half_rn(v.y));
    ho.z = __half_as_ushort(__float2half_rn(v.z));
    ho.w = __half_as_ushort(__float2half_rn(v.w));
    ((ushort4*)h)[i] = ho;
}

// ───────── bias concat: bqkv = [bq | bk | bv] ─────────
__global__ __launch_bounds__(256) void bias_concat(
    const float* __restrict__ bq, const float* __restrict__ bk,
    const float* __restrict__ bv, float* __restrict__ dst)
{
    int i = blockIdx.x * blockDim.x + threadIdx.x;
    if (i >= NQKV) return;
    float v;
    if (i < 4096)      v = bq[i];
    else if (i < 5120) v = bk[i - 4096];
    else               v = bv[i - 5120];
    dst[i] = v;
}

// ───────── fp16 2-pass GEMM: TMA + mma.sync ─────────
// C[M,N] = (Ah+Al)[M,K] · W16[N,K]^T + bias, fp32 accum.
// CTA tile 128×256, 8 warps × (64m×64n), K-chunk 64 (128B rows, SW128),
// 3-stage TMA pipeline.
#define CHK 64
#define SOFF_AH 0u
#define SOFF_AL 16384u
#define SOFF_B  32768u
#define STB 65536u
#define SM_CTRL (3u*STB)
#define GSMEM (3*65536 + 64)

__global__ __launch_bounds__(256, 1) void hgemm(
    const __grid_constant__ CUtensorMap tAh,
    const __grid_constant__ CUtensorMap tAl,
    const __grid_constant__ CUtensorMap tB,
    const float* __restrict__ bias, float* __restrict__ C,
    int M, int N_, int K)
{
    extern __shared__ __align__(1024) char smem[];
    const u32 sb   = smem_u32(smem);
    const int tid  = threadIdx.x;
    const int wid  = tid >> 5;
    const int lane = tid & 31;
    const int m0   = blockIdx.y * 128;
    const int n0   = blockIdx.x * 256;
    const int wm   = (wid & 1) * 64;
    const int wn   = (wid >> 1) * 64;
    const int nch  = K / CHK;

    float acc[4][8][4];
    #pragma unroll
    for (int i = 0; i < 4; i++)
        #pragma unroll
        for (int j = 0; j < 8; j++)
            #pragma unroll
            for (int t = 0; t < 4; t++) acc[i][j][t] = 0.f;

    if (tid == 0) {
        MBAR_INIT(sb + SM_CTRL, 1);
        MBAR_INIT(sb + SM_CTRL + 8, 1);
        MBAR_INIT(sb + SM_CTRL + 16, 1);
    }
    __syncthreads();

    auto issue = [&](int c) {
        if (tid == 0) {
            const int st   = c % 3;
            const u32 mbar = sb + SM_CTRL + st * 8;
            const u32 s0   = sb + st * STB;
            MBAR_EXPECT(mbar, 65536u);
            int kc = c * CHK;
            tma2d(s0 + SOFF_AH, &tAh, kc, m0, mbar);
            tma2d(s0 + SOFF_AL, &tAl, kc, m0, mbar);
            tma2d(s0 + SOFF_B,  &tB,  kc, n0, mbar);
        }
    };

    issue(0);
    issue(1);
    issue(2);

    for (int c = 0; c < nch; c++) {
        const int st = c % 3;
        mbar_wait(sb + SM_CTRL + st * 8, (c / 3) & 1);
        const u32 s0 = sb + st * STB;

        #pragma unroll
        for (int ks = 0; ks < 4; ks++) {
            const int k0 = ks * 16;
            u32 ah[4][4], al[4][4], b[4][4];
            #pragma unroll
            for (int ma = 0; ma < 4; ma++) {
                int row  = wm + ma * 16 + ((lane >> 3) & 1) * 8 + (lane & 7);
                int colB = (k0 + (lane >> 4) * 8) * 2;
                u32 off  = SWZ(row * 128 + colB);
                ldsm4(s0 + SOFF_AH + off, ah[ma]);
                ldsm4(s0 + SOFF_AL + off, al[ma]);
            }
            #pragma unroll
            for (int j = 0; j < 4; j++) {
                int row  = wn + j * 16 + (lane >> 4) * 8 + (lane & 7);
                int colB = (k0 + ((lane >> 3) & 1) * 8) * 2;
                u32 off  = SWZ(row * 128 + colB);
                ldsm4(s0 + SOFF_B + off, b[j]);
            }
            #pragma unroll
            for (int j = 0; j < 4; j++)
                #pragma unroll
                for (int ma = 0; ma < 4; ma++) {
                    mma16816(acc[ma][j*2+0], ah[ma], &b[j][0]);
                    mma16816(acc[ma][j*2+1], ah[ma], &b[j][2]);
                }
            #pragma unroll
            for (int j = 0; j < 4; j++)
                #pragma unroll
                for (int ma = 0; ma < 4; ma++) {
                    mma16816(acc[ma][j*2+0], al[ma], &b[j][0]);
                    mma16816(acc[ma][j*2+1], al[ma], &b[j][2]);
                }
        }
        __syncthreads();
        if (c + 3 < nch) issue(c + 3);
    }

    #pragma unroll
    for (int ma = 0; ma < 4; ma++) {
        #pragma unroll
        for (int nb = 0; nb < 8; nb++) {
            int row = m0 + wm + ma * 16 + (lane >> 2);
            int col = n0 + wn + nb * 8 + (lane & 3) * 2;
            float b0 = bias[col], b1 = bias[col + 1];
            float* p = C + (size_t)row * N_ + col;
            *(float2*)p = make_float2(acc[ma][nb][0] + b0, acc[ma][nb][1] + b1);
            *(float2*)(p + 8 * (size_t)N_) =
                make_float2(acc[ma][nb][2] + b0, acc[ma][nb][3] + b1);
        }
    }
}

// ───────── per-token 16×16 attention + softmax + q-sum + shuffle ─────────
// reads the fused qkv buffer; writes fp16 hi/lo z.
__global__ __launch_bounds__(256) void attn_kernel(
    const float* __restrict__ qkv,
    __half* __restrict__ zh, __half* __restrict__ zl)
{
    __shared__ float sk[HH][66];
    __shared__ float sv[HH][66];
    __shared__ float sq[QQ][HH][66];
    __shared__ float ss[QQ*HH][HH + 1];
    __shared__ float sp_[QQ*HH][HH + 1];

    const int n   = blockIdx.x;
    const int b   = n >> 11;
    const int sp  = n & 2047;
    const int tid = threadIdx.x;

    {
        const float4* base4 = (const float4*)(qkv + (size_t)n * NQKV);
        // q: float4 indices [0,1024); k: [1024,1280); v: [1280,1536)
        #pragma unroll
        for (int j = 0; j < 4; j++) {
            int idx = tid + j * 256;
            int qi = idx >> 8, rr = (idx >> 4) & 15, cc = (idx & 15) * 4;
            float4 qf = base4[idx];
            sq[qi][rr][cc]   = qf.x; sq[qi][rr][cc+1] = qf.y;
            sq[qi][rr][cc+2] = qf.z; sq[qi][rr][cc+3] = qf.w;
        }
        int r = tid >> 4, c4 = (tid & 15) * 4;
        float4 kf = base4[1024 + tid];
        float4 vf = base4[1280 + tid];
        sk[r][c4] = kf.x; sk[r][c4+1] = kf.y; sk[r][c4+2] = kf.z; sk[r][c4+3] = kf.w;
        sv[r][c4] = vf.x; sv[r][c4+1] = vf.y; sv[r][c4+2] = vf.z; sv[r][c4+3] = vf.w;
    }
    __syncthreads();

    {
        const int h = tid >> 4, g = tid & 15;
        const float2* kr = (const float2*)&sk[g][0];
        #pragma unroll
        for (int qi = 0; qi < QQ; qi++) {
            const float2* qr = (const float2*)&sq[qi][h][0];
            float s = 0.f;
            #pragma unroll
            for (int dd = 0; dd < 32; dd++) {
                float2 a = qr[dd], c = kr[dd];
                s += a.x * c.x + a.y * c.y;
            }
            ss[qi * HH + h][g] = s * 0.125f;
        }
    }
    __syncthreads();

    if (tid < QQ * HH) {
        float m = -1e30f;
        #pragma unroll
        for (int g = 0; g < HH; g++) m = fmaxf(m, ss[tid][g]);
        float e[HH], sum = 0.f;
        #pragma unroll
        for (int g = 0; g < HH; g++) { e[g] = __expf(ss[tid][g] - m); sum += e[g]; }
        float inv = 1.f / sum;
        #pragma unroll
        for (int g = 0; g < HH; g++) sp_[tid][g] = e[g] * inv;
    }
    __syncthreads();

    const int d  = tid & 63;
    const int hq = tid >> 6;
    #pragma unroll
    for (int j = 0; j < 4; j++) {
        int h = hq * 4 + j;
        float o = 0.f;
        #pragma unroll
        for (int qi = 0; qi < QQ; qi++) {
            const float* pr = sp_[qi * HH + h];
            #pragma unroll
            for (int g = 0; g < HH; g++) o += pr[g] * sv[g][d];
        }
        int sfin = h * 128 + (sp >> 4);
        int e    = ((sp & 15) << 6) + d;
        size_t idx = ((size_t)b * SS + sfin) * EE + e;
        __half hb = __float2half_rn(o);
        zh[idx] = hb;
        zl[idx] = __float2half_rn(o - __half2float(hb));
    }
}

// ───────── host: TMA descriptor builder ─────────
typedef CUresult (*PFN_encode)(
    CUtensorMap*, CUtensorMapDataType, cuuint32_t, void*,
    const cuuint64_t*, const cuuint64_t*, const cuuint32_t*, const cuuint32_t*,
    CUtensorMapInterleave, CUtensorMapSwizzle, CUtensorMapL2promotion,
    CUtensorMapFloatOOBfill);

static CUtensorMap mk_map16(PFN_encode enc, void* base, u64 rows, u32 boxrows) {
    CUtensorMap m;
    cuuint64_t dims[2]    = {(cuuint64_t)EE, rows};
    cuuint64_t strides[1] = {(cuuint64_t)EE * 2};
    cuuint32_t box[2]     = {64u, boxrows};
    cuuint32_t es[2]      = {1u, 1u};
    enc(&m, CU_TENSOR_MAP_DATA_TYPE_FLOAT16, 2, base, dims, strides, box, es,
        CU_TENSOR_MAP_INTERLEAVE_NONE, CU_TENSOR_MAP_SWIZZLE_128B,
        CU_TENSOR_MAP_L2_PROMOTION_L2_128B, CU_TENSOR_MAP_FLOAT_OOB_FILL_NONE);
    return m;
}

extern "C" void kernel_launch(void* const* d_in, const int* in_sizes, int n_in,
                              void* d_out, int out_size)
{
    const float* x  = (const float*)d_in[0];
    const float* Wq = (const float*)d_in[1];
    const float* bq = (const float*)d_in[2];
    const float* Wk = (const float*)d_in[3];
    const float* bk = (const float*)d_in[4];
    const float* Wv = (const float*)d_in[5];
    const float* bv = (const float*)d_in[6];
    const float* Wo = (const float*)d_in[7];
    const float* bo = (const float*)d_in[8];
    float* out = (float*)d_out;

    float *pqkv, *pbqkv;
    __half *xh, *xl, *zh, *zl, *wqkv, *wo;
    cudaGetSymbolAddress((void**)&pqkv,  g_qkv);
    cudaGetSymbolAddress((void**)&pbqkv, g_bqkv);
    cudaGetSymbolAddress((void**)&xh, g_xh);  cudaGetSymbolAddress((void**)&xl, g_xl);
    cudaGetSymbolAddress((void**)&zh, g_zh);  cudaGetSymbolAddress((void**)&zl, g_zl);
    cudaGetSymbolAddress((void**)&wqkv, g_wqkv);
    cudaGetSymbolAddress((void**)&wo, g_wo);

    PFN_encode enc = 0;
    cudaDriverEntryPointQueryResult qr;
    cudaGetDriverEntryPoint("cuTensorMapEncodeTiled", (void**)&enc,
                            cudaEnableDefault, &qr);

    CUtensorMap mXh = mk_map16(enc, xh, MM, 128);
    CUtensorMap mXl = mk_map16(enc, xl, MM, 128);
    CUtensorMap mZh = mk_map16(enc, zh, MM, 128);
    CUtensorMap mZl = mk_map16(enc, zl, MM, 128);
    CUtensorMap mW  = mk_map16(enc, wqkv, NQKV, 256);
    CUtensorMap mO  = mk_map16(enc, wo, EE, 256);

    cudaFuncSetAttribute(hgemm, cudaFuncAttributeMaxDynamicSharedMemorySize, GSMEM);

    dim3 blk(256);
    split16<<<(MM*EE/4 + 255)/256, blk>>>(x, xh, xl, MM*EE/4);
    conv16<<<(QQ*EE*EE/4 + 255)/256, blk>>>(Wq, wqkv,                      QQ*EE*EE/4);
    conv16<<<(EE*EE/4 + 255)/256, blk>>>(Wk, wqkv + (size_t)4096*EE,       EE*EE/4);
    conv16<<<(EE*EE/4 + 255)/256, blk>>>(Wv, wqkv + (size_t)5120*EE,       EE*EE/4);
    conv16<<<(EE*EE/4 + 255)/256, blk>>>(Wo, wo,                           EE*EE/4);
    bias_concat<<<(NQKV + 255)/256, blk>>>(bq, bk, bv, pbqkv);

    // fused Q|K|V projection: one GEMM, N = 6144
    hgemm<<<dim3(NQKV/256, MM/128), blk, GSMEM>>>(mXh, mXl, mW, pbqkv, pqkv, MM, NQKV, EE);

    attn_kernel<<<MM, blk>>>(pqkv, zh, zl);

    hgemm<<<dim3(EE/256, MM/128), blk, GSMEM>>>(mZh, mZl, mO, bo, out, MM, EE, EE);
}

// round 10
// speedup vs baseline: 1.2651x; 1.2651x over previous
#include <cuda_runtime.h>
#include <cuda.h>
#include <cuda_fp16.h>

typedef unsigned int u32;
typedef unsigned long long u64;

#define BB 4
#define SS 2048
#define EE 1024
#define HH 16
#define DD 64
#define QQ 4
#define MM (BB*SS)     /* 8192 tokens */
#define NQKV 6144      /* 4096 q + 1024 k + 1024 v */
#define NQK  5120      /* q|k : 1-pass precision class */

// ───────── scratch (allocation-free rule: __device__ globals) ─────────
__device__ float g_qkv[(size_t)MM * NQKV];
__device__ float g_bqkv[NQKV];

__device__ __half g_xh[(size_t)MM*EE],  g_xl[(size_t)MM*EE];
__device__ __half g_zh[(size_t)MM*EE],  g_zl[(size_t)MM*EE];
__device__ __half g_wqkv[(size_t)NQKV*EE];      // Wq|Wk|Wv
__device__ __half g_wo[(size_t)EE*EE];

__device__ __forceinline__ u32 smem_u32(const void* p) {
    u32 a;
    asm("{ .reg .u64 t; cvta.to.shared.u64 t, %1; cvt.u32.u64 %0, t; }"
        : "=r"(a) : "l"(p));
    return a;
}
__device__ __forceinline__ void ldsm4(u32 addr, u32* r) {
    asm volatile("ldmatrix.sync.aligned.m8n8.x4.shared.b16 {%0,%1,%2,%3}, [%4];"
                 : "=r"(r[0]), "=r"(r[1]), "=r"(r[2]), "=r"(r[3]) : "r"(addr));
}
__device__ __forceinline__ void mma16816(float* c, const u32* a, const u32* b) {
    asm volatile(
        "mma.sync.aligned.m16n8k16.row.col.f32.f16.f16.f32 "
        "{%0,%1,%2,%3}, {%4,%5,%6,%7}, {%8,%9}, {%0,%1,%2,%3};"
        : "+f"(c[0]), "+f"(c[1]), "+f"(c[2]), "+f"(c[3])
        : "r"(a[0]), "r"(a[1]), "r"(a[2]), "r"(a[3]), "r"(b[0]), "r"(b[1]));
}
__device__ __forceinline__ void tma2d(u32 saddr, const CUtensorMap* m,
                                      int cx, int cy, u32 mbar) {
    asm volatile(
        "cp.async.bulk.tensor.2d.shared::cta.global.tile.mbarrier::complete_tx::bytes "
        "[%0], [%1, {%2, %3}], [%4];"
        :: "r"(saddr), "l"(m), "r"(cx), "r"(cy), "r"(mbar) : "memory");
}
#define MBAR_INIT(addr, cnt) \
    asm volatile("mbarrier.init.shared.b64 [%0], %1;" :: "r"(addr), "r"(cnt) : "memory")
#define MBAR_EXPECT(addr, bytes) \
    asm volatile("mbarrier.arrive.expect_tx.shared.b64 _, [%0], %1;" \
                 :: "r"(addr), "r"(bytes) : "memory")
__device__ __forceinline__ void mbar_wait(u32 addr, u32 parity) {
    asm volatile(
        "{\n\t.reg .pred P;\n\t"
        "W%=:\n\t"
        "mbarrier.try_wait.parity.acquire.cta.shared::cta.b64 P, [%0], %1, 0x989680;\n\t"
        "@P bra D%=;\n\t"
        "bra W%=;\n\t"
        "D%=:\n\t}"
        :: "r"(addr), "r"(parity) : "memory");
}
#define SWZ(off) ((u32)(off) ^ ((((u32)(off)) >> 3) & 0x70))

// ───────── fp32 → fp16 hi/lo split ─────────
__global__ __launch_bounds__(256) void split16(
    const float* __restrict__ s, __half* __restrict__ h,
    __half* __restrict__ l, int n4)
{
    int i = blockIdx.x * blockDim.x + threadIdx.x;
    if (i >= n4) return;
    float4 v = ((const float4*)s)[i];
    float f[4] = {v.x, v.y, v.z, v.w};
    ushort4 ho, lo;
    unsigned short* hp = &ho.x; unsigned short* lp = &lo.x;
    #pragma unroll
    for (int j = 0; j < 4; j++) {
        __half hb = __float2half_rn(f[j]);
        __half lb = __float2half_rn(f[j] - __half2float(hb));
        hp[j] = __half_as_ushort(hb);
        lp[j] = __half_as_ushort(lb);
    }
    ((ushort4*)h)[i] = ho;
    ((ushort4*)l)[i] = lo;
}

// ───────── fp32 → fp16 (single) ─────────
__global__ __launch_bounds__(256) void conv16(
    const float* __restrict__ s, __half* __restrict__ h, int n4)
{
    int i = blockIdx.x * blockDim.x + threadIdx.x;
    if (i >= n4) return;
    float4 v = ((const float4*)s)[i];
    ushort4 ho;
    ho.x = __half_as_ushort(__float2half_rn(v.x));
    ho.y = __half_as_ushort(__float2half_rn(v.y));
    ho.z = __half_as_ushort(__float2half_rn(v.z));
    ho.w = __half_as_ushort(__float2half_rn(v.w));
    ((ushort4*)h)[i] = ho;
}

__global__ __launch_bounds__(256) void bias_concat(
    const float* __restrict__ bq, const float* __restrict__ bk,
    const float* __restrict__ bv, float* __restrict__ dst)
{
    int i = blockIdx.x * blockDim.x + threadIdx.x;
    if (i >= NQKV) return;
    float v;
    if (i < 4096)      v = bq[i];
    else if (i < 5120) v = bk[i - 4096];
    else               v = bv[i - 5120];
    dst[i] = v;
}

// ═════════ 1-PASS fp16 GEMM (q|k path): 4-stage TMA ═════════
#define CHK 64
#define S1_A 0u
#define S1_B 16384u
#define STB1 49152u               /* 48 KB per stage */
#define S1_CTRL (4u*STB1)
#define GSMEM1 (4*49152 + 64)

__global__ __launch_bounds__(256, 1) void hgemm1(
    const __grid_constant__ CUtensorMap tA,
    const __grid_constant__ CUtensorMap tB,
    const float* __restrict__ bias, float* __restrict__ C,
    int N_, int K, int ny0)
{
    extern __shared__ __align__(1024) char smem[];
    const u32 sb   = smem_u32(smem);
    const int tid  = threadIdx.x;
    const int wid  = tid >> 5;
    const int lane = tid & 31;
    const int m0   = blockIdx.y * 128;
    const int n0   = blockIdx.x * 256;
    const int wm   = (wid & 1) * 64;
    const int wn   = (wid >> 1) * 64;
    const int nch  = K / CHK;

    float acc[4][8][4];
    #pragma unroll
    for (int i = 0; i < 4; i++)
        #pragma unroll
        for (int j = 0; j < 8; j++)
            #pragma unroll
            for (int t = 0; t < 4; t++) acc[i][j][t] = 0.f;

    if (tid == 0) {
        #pragma unroll
        for (int s = 0; s < 4; s++) MBAR_INIT(sb + S1_CTRL + s * 8, 1);
    }
    __syncthreads();

    auto issue = [&](int c) {
        if (tid == 0) {
            const int st   = c & 3;
            const u32 mbar = sb + S1_CTRL + st * 8;
            const u32 s0   = sb + st * STB1;
            MBAR_EXPECT(mbar, 49152u);
            int kc = c * CHK;
            tma2d(s0 + S1_A, &tA, kc, m0, mbar);
            tma2d(s0 + S1_B, &tB, kc, ny0 + n0, mbar);
        }
    };

    issue(0); issue(1); issue(2); issue(3);

    for (int c = 0; c < nch; c++) {
        const int st = c & 3;
        mbar_wait(sb + S1_CTRL + st * 8, (c >> 2) & 1);
        const u32 s0 = sb + st * STB1;

        #pragma unroll
        for (int ks = 0; ks < 4; ks++) {
            const int k0 = ks * 16;
            u32 a[4][4], b[4][4];
            #pragma unroll
            for (int ma = 0; ma < 4; ma++) {
                int row  = wm + ma * 16 + ((lane >> 3) & 1) * 8 + (lane & 7);
                int colB = (k0 + (lane >> 4) * 8) * 2;
                ldsm4(s0 + S1_A + SWZ(row * 128 + colB), a[ma]);
            }
            #pragma unroll
            for (int j = 0; j < 4; j++) {
                int row  = wn + j * 16 + (lane >> 4) * 8 + (lane & 7);
                int colB = (k0 + ((lane >> 3) & 1) * 8) * 2;
                ldsm4(s0 + S1_B + SWZ(row * 128 + colB), b[j]);
            }
            #pragma unroll
            for (int j = 0; j < 4; j++)
                #pragma unroll
                for (int ma = 0; ma < 4; ma++) {
                    mma16816(acc[ma][j*2+0], a[ma], &b[j][0]);
                    mma16816(acc[ma][j*2+1], a[ma], &b[j][2]);
                }
        }
        __syncthreads();
        if (c + 4 < nch) issue(c + 4);
    }

    #pragma unroll
    for (int ma = 0; ma < 4; ma++) {
        #pragma unroll
        for (int nb = 0; nb < 8; nb++) {
            int row = m0 + wm + ma * 16 + (lane >> 2);
            int col = n0 + wn + nb * 8 + (lane & 3) * 2;
            float b0 = bias[col], b1 = bias[col + 1];
            float* p = C + (size_t)row * N_ + col;
            *(float2*)p = make_float2(acc[ma][nb][0] + b0, acc[ma][nb][1] + b1);
            *(float2*)(p + 8 * (size_t)N_) =
                make_float2(acc[ma][nb][2] + b0, acc[ma][nb][3] + b1);
        }
    }
}

// ═════════ 2-PASS split-x fp16 GEMM (v + O path): 3-stage TMA ═════════
#define SOFF_AH 0u
#define SOFF_AL 16384u
#define SOFF_B  32768u
#define STB 65536u
#define SM_CTRL (3u*STB)
#define GSMEM (3*65536 + 64)

__global__ __launch_bounds__(256, 1) void hgemm2(
    const __grid_constant__ CUtensorMap tAh,
    const __grid_constant__ CUtensorMap tAl,
    const __grid_constant__ CUtensorMap tB,
    const float* __restrict__ bias, float* __restrict__ C,
    int N_, int K, int ny0)
{
    extern __shared__ __align__(1024) char smem[];
    const u32 sb   = smem_u32(smem);
    const int tid  = threadIdx.x;
    const int wid  = tid >> 5;
    const int lane = tid & 31;
    const int m0   = blockIdx.y * 128;
    const int n0   = blockIdx.x * 256;
    const int wm   = (wid & 1) * 64;
    const int wn   = (wid >> 1) * 64;
    const int nch  = K / CHK;

    float acc[4][8][4];
    #pragma unroll
    for (int i = 0; i < 4; i++)
        #pragma unroll
        for (int j = 0; j < 8; j++)
            #pragma unroll
            for (int t = 0; t < 4; t++) acc[i][j][t] = 0.f;

    if (tid == 0) {
        MBAR_INIT(sb + SM_CTRL, 1);
        MBAR_INIT(sb + SM_CTRL + 8, 1);
        MBAR_INIT(sb + SM_CTRL + 16, 1);
    }
    __syncthreads();

    auto issue = [&](int c) {
        if (tid == 0) {
            const int st   = c % 3;
            const u32 mbar = sb + SM_CTRL + st * 8;
            const u32 s0   = sb + st * STB;
            MBAR_EXPECT(mbar, 65536u);
            int kc = c * CHK;
            tma2d(s0 + SOFF_AH, &tAh, kc, m0, mbar);
            tma2d(s0 + SOFF_AL, &tAl, kc, m0, mbar);
            tma2d(s0 + SOFF_B,  &tB,  kc, ny0 + n0, mbar);
        }
    };

    issue(0); issue(1); issue(2);

    for (int c = 0; c < nch; c++) {
        const int st = c % 3;
        mbar_wait(sb + SM_CTRL + st * 8, (c / 3) & 1);
        const u32 s0 = sb + st * STB;

        #pragma unroll
        for (int ks = 0; ks < 4; ks++) {
            const int k0 = ks * 16;
            u32 ah[4][4], al[4][4], b[4][4];
            #pragma unroll
            for (int ma = 0; ma < 4; ma++) {
                int row  = wm + ma * 16 + ((lane >> 3) & 1) * 8 + (lane & 7);
                int colB = (k0 + (lane >> 4) * 8) * 2;
                u32 off  = SWZ(row * 128 + colB);
                ldsm4(s0 + SOFF_AH + off, ah[ma]);
                ldsm4(s0 + SOFF_AL + off, al[ma]);
            }
            #pragma unroll
            for (int j = 0; j < 4; j++) {
                int row  = wn + j * 16 + (lane >> 4) * 8 + (lane & 7);
                int colB = (k0 + ((lane >> 3) & 1) * 8) * 2;
                ldsm4(s0 + SOFF_B + SWZ(row * 128 + colB), b[j]);
            }
            #pragma unroll
            for (int j = 0; j < 4; j++)
                #pragma unroll
                for (int ma = 0; ma < 4; ma++) {
                    mma16816(acc[ma][j*2+0], ah[ma], &b[j][0]);
                    mma16816(acc[ma][j*2+1], ah[ma], &b[j][2]);
                }
            #pragma unroll
            for (int j = 0; j < 4; j++)
                #pragma unroll
                for (int ma = 0; ma < 4; ma++) {
                    mma16816(acc[ma][j*2+0], al[ma], &b[j][0]);
                    mma16816(acc[ma][j*2+1], al[ma], &b[j][2]);
                }
        }
        __syncthreads();
        if (c + 3 < nch) issue(c + 3);
    }

    #pragma unroll
    for (int ma = 0; ma < 4; ma++) {
        #pragma unroll
        for (int nb = 0; nb < 8; nb++) {
            int row = m0 + wm + ma * 16 + (lane >> 2);
            int col = n0 + wn + nb * 8 + (lane & 3) * 2;
            float b0 = bias[col], b1 = bias[col + 1];
            float* p = C + (size_t)row * N_ + col;
            *(float2*)p = make_float2(acc[ma][nb][0] + b0, acc[ma][nb][1] + b1);
            *(float2*)(p + 8 * (size_t)N_) =
                make_float2(acc[ma][nb][2] + b0, acc[ma][nb][3] + b1);
        }
    }
}

// ───────── per-token 16×16 attention + softmax + q-sum + shuffle ─────────
__global__ __launch_bounds__(256) void attn_kernel(
    const float* __restrict__ qkv,
    __half* __restrict__ zh, __half* __restrict__ zl)
{
    __shared__ float sk[HH][66];
    __shared__ float sv[HH][66];
    __shared__ float sq[QQ][HH][66];
    __shared__ float ss[QQ*HH][HH + 1];
    __shared__ float sp_[QQ*HH][HH + 1];

    const int n   = blockIdx.x;
    const int b   = n >> 11;
    const int sp  = n & 2047;
    const int tid = threadIdx.x;

    {
        const float4* base4 = (const float4*)(qkv + (size_t)n * NQKV);
        #pragma unroll
        for (int j = 0; j < 4; j++) {
            int idx = tid + j * 256;
            int qi = idx >> 8, rr = (idx >> 4) & 15, cc = (idx & 15) * 4;
            float4 qf = base4[idx];
            sq[qi][rr][cc]   = qf.x; sq[qi][rr][cc+1] = qf.y;
            sq[qi][rr][cc+2] = qf.z; sq[qi][rr][cc+3] = qf.w;
        }
        int r = tid >> 4, c4 = (tid & 15) * 4;
        float4 kf = base4[1024 + tid];
        float4 vf = base4[1280 + tid];
        sk[r][c4] = kf.x; sk[r][c4+1] = kf.y; sk[r][c4+2] = kf.z; sk[r][c4+3] = kf.w;
        sv[r][c4] = vf.x; sv[r][c4+1] = vf.y; sv[r][c4+2] = vf.z; sv[r][c4+3] = vf.w;
    }
    __syncthreads();

    {
        const int h = tid >> 4, g = tid & 15;
        const float2* kr = (const float2*)&sk[g][0];
        #pragma unroll
        for (int qi = 0; qi < QQ; qi++) {
            const float2* qr = (const float2*)&sq[qi][h][0];
            float s = 0.f;
            #pragma unroll
            for (int dd = 0; dd < 32; dd++) {
                float2 a = qr[dd], c = kr[dd];
                s += a.x * c.x + a.y * c.y;
            }
            ss[qi * HH + h][g] = s * 0.125f;
        }
    }
    __syncthreads();

    if (tid < QQ * HH) {
        float m = -1e30f;
        #pragma unroll
        for (int g = 0; g < HH; g++) m = fmaxf(m, ss[tid][g]);
        float e[HH], sum = 0.f;
        #pragma unroll
        for (int g = 0; g < HH; g++) { e[g] = __expf(ss[tid][g] - m); sum += e[g]; }
        float inv = 1.f / sum;
        #pragma unroll
        for (int g = 0; g < HH; g++) sp_[tid][g] = e[g] * inv;
    }
    __syncthreads();

    const int d  = tid & 63;
    const int hq = tid >> 6;
    #pragma unroll
    for (int j = 0; j < 4; j++) {
        int h = hq * 4 + j;
        float o = 0.f;
        #pragma unroll
        for (int qi = 0; qi < QQ; qi++) {
            const float* pr = sp_[qi * HH + h];
            #pragma unroll
            for (int g = 0; g < HH; g++) o += pr[g] * sv[g][d];
        }
        int sfin = h * 128 + (sp >> 4);
        int e    = ((sp & 15) << 6) + d;
        size_t idx = ((size_t)b * SS + sfin) * EE + e;
        __half hb = __float2half_rn(o);
        zh[idx] = hb;
        zl[idx] = __float2half_rn(o - __half2float(hb));
    }
}

// ───────── host ─────────
typedef CUresult (*PFN_encode)(
    CUtensorMap*, CUtensorMapDataType, cuuint32_t, void*,
    const cuuint64_t*, const cuuint64_t*, const cuuint32_t*, const cuuint32_t*,
    CUtensorMapInterleave, CUtensorMapSwizzle, CUtensorMapL2promotion,
    CUtensorMapFloatOOBfill);

static CUtensorMap mk_map16(PFN_encode enc, void* base, u64 rows, u32 boxrows) {
    CUtensorMap m;
    cuuint64_t dims[2]    = {(cuuint64_t)EE, rows};
    cuuint64_t strides[1] = {(cuuint64_t)EE * 2};
    cuuint32_t box[2]     = {64u, boxrows};
    cuuint32_t es[2]      = {1u, 1u};
    enc(&m, CU_TENSOR_MAP_DATA_TYPE_FLOAT16, 2, base, dims, strides, box, es,
        CU_TENSOR_MAP_INTERLEAVE_NONE, CU_TENSOR_MAP_SWIZZLE_128B,
        CU_TENSOR_MAP_L2_PROMOTION_L2_128B, CU_TENSOR_MAP_FLOAT_OOB_FILL_NONE);
    return m;
}

extern "C" void kernel_launch(void* const* d_in, const int* in_sizes, int n_in,
                              void* d_out, int out_size)
{
    const float* x  = (const float*)d_in[0];
    const float* Wq = (const float*)d_in[1];
    const float* bq = (const float*)d_in[2];
    const float* Wk = (const float*)d_in[3];
    const float* bk = (const float*)d_in[4];
    const float* Wv = (const float*)d_in[5];
    const float* bv = (const float*)d_in[6];
    const float* Wo = (const float*)d_in[7];
    const float* bo = (const float*)d_in[8];
    float* out = (float*)d_out;

    float *pqkv, *pbqkv;
    __half *xh, *xl, *zh, *zl, *wqkv, *wo;
    cudaGetSymbolAddress((void**)&pqkv,  g_qkv);
    cudaGetSymbolAddress((void**)&pbqkv, g_bqkv);
    cudaGetSymbolAddress((void**)&xh, g_xh);  cudaGetSymbolAddress((void**)&xl, g_xl);
    cudaGetSymbolAddress((void**)&zh, g_zh);  cudaGetSymbolAddress((void**)&zl, g_zl);
    cudaGetSymbolAddress((void**)&wqkv, g_wqkv);
    cudaGetSymbolAddress((void**)&wo, g_wo);

    PFN_encode enc = 0;
    cudaDriverEntryPointQueryResult qr;
    cudaGetDriverEntryPoint("cuTensorMapEncodeTiled", (void**)&enc,
                            cudaEnableDefault, &qr);

    CUtensorMap mXh = mk_map16(enc, xh, MM, 128);
    CUtensorMap mXl = mk_map16(enc, xl, MM, 128);
    CUtensorMap mZh = mk_map16(enc, zh, MM, 128);
    CUtensorMap mZl = mk_map16(enc, zl, MM, 128);
    CUtensorMap mW  = mk_map16(enc, wqkv, NQKV, 256);
    CUtensorMap mO  = mk_map16(enc, wo, EE, 256);

    cudaFuncSetAttribute(hgemm1, cudaFuncAttributeMaxDynamicSharedMemorySize, GSMEM1);
    cudaFuncSetAttribute(hgemm2, cudaFuncAttributeMaxDynamicSharedMemorySize, GSMEM);

    dim3 blk(256);
    split16<<<(MM*EE/4 + 255)/256, blk>>>(x, xh, xl, MM*EE/4);
    conv16<<<(QQ*EE*EE/4 + 255)/256, blk>>>(Wq, wqkv,                QQ*EE*EE/4);
    conv16<<<(EE*EE/4 + 255)/256, blk>>>(Wk, wqkv + (size_t)4096*EE, EE*EE/4);
    conv16<<<(EE*EE/4 + 255)/256, blk>>>(Wv, wqkv + (size_t)5120*EE, EE*EE/4);
    conv16<<<(EE*EE/4 + 255)/256, blk>>>(Wo, wo,                     EE*EE/4);
    bias_concat<<<(NQKV + 255)/256, blk>>>(bq, bk, bv, pbqkv);

    // Q|K: 1-pass fp16 (softmax-attenuated error path), N=5120
    hgemm1<<<dim3(NQK/256, MM/128), blk, GSMEM1>>>(
        mXh, mW, pbqkv, pqkv, NQKV, EE, 0);
    // V: 2-pass split-x (direct output path), N=1024, into cols [5120,6144)
    hgemm2<<<dim3((NQKV-NQK)/256, MM/128), blk, GSMEM>>>(
        mXh, mXl, mW, pbqkv + NQK, pqkv + NQK, NQKV, EE, NQK);

    attn_kernel<<<MM, blk>>>(pqkv, zh, zl);

    // O: 2-pass split-z (direct output path)
    hgemm2<<<dim3(EE/256, MM/128), blk, GSMEM>>>(
        mZh, mZl, mO, bo, out, EE, EE, 0);
}

// round 11
// speedup vs baseline: 1.3650x; 1.0790x over previous
#include <cuda_runtime.h>
#include <cuda.h>
#include <cuda_fp16.h>

typedef unsigned int u32;
typedef unsigned long long u64;

#define BB 4
#define SS 2048
#define EE 1024
#define HH 16
#define DD 64
#define QQ 4
#define MM (BB*SS)     /* 8192 tokens */
#define NQKV 6144
#define NQK  5120      /* q|k fp16 1-pass class */

// ───────── scratch (allocation-free rule: __device__ globals) ─────────
__device__ __half g_qk[(size_t)MM * NQK];      // q|k projection, fp16
__device__ float  g_v [(size_t)MM * EE];       // v projection, fp32 (protected)
__device__ __half g_z [(size_t)MM * EE];       // attn output, fp16
__device__ float  g_bqkv[NQKV];

__device__ __half g_xh[(size_t)MM*EE], g_xl[(size_t)MM*EE];
__device__ __half g_wqkv[(size_t)NQKV*EE];     // Wq|Wk|Wv fp16
__device__ __half g_wo[(size_t)EE*EE];

__device__ __forceinline__ u32 smem_u32(const void* p) {
    u32 a;
    asm("{ .reg .u64 t; cvta.to.shared.u64 t, %1; cvt.u32.u64 %0, t; }"
        : "=r"(a) : "l"(p));
    return a;
}
__device__ __forceinline__ void ldsm4(u32 addr, u32* r) {
    asm volatile("ldmatrix.sync.aligned.m8n8.x4.shared.b16 {%0,%1,%2,%3}, [%4];"
                 : "=r"(r[0]), "=r"(r[1]), "=r"(r[2]), "=r"(r[3]) : "r"(addr));
}
__device__ __forceinline__ void mma16816(float* c, const u32* a, const u32* b) {
    asm volatile(
        "mma.sync.aligned.m16n8k16.row.col.f32.f16.f16.f32 "
        "{%0,%1,%2,%3}, {%4,%5,%6,%7}, {%8,%9}, {%0,%1,%2,%3};"
        : "+f"(c[0]), "+f"(c[1]), "+f"(c[2]), "+f"(c[3])
        : "r"(a[0]), "r"(a[1]), "r"(a[2]), "r"(a[3]), "r"(b[0]), "r"(b[1]));
}
__device__ __forceinline__ void tma2d(u32 saddr, const CUtensorMap* m,
                                      int cx, int cy, u32 mbar) {
    asm volatile(
        "cp.async.bulk.tensor.2d.shared::cta.global.tile.mbarrier::complete_tx::bytes "
        "[%0], [%1, {%2, %3}], [%4];"
        :: "r"(saddr), "l"(m), "r"(cx), "r"(cy), "r"(mbar) : "memory");
}
#define MBAR_INIT(addr, cnt) \
    asm volatile("mbarrier.init.shared.b64 [%0], %1;" :: "r"(addr), "r"(cnt) : "memory")
#define MBAR_EXPECT(addr, bytes) \
    asm volatile("mbarrier.arrive.expect_tx.shared.b64 _, [%0], %1;" \
                 :: "r"(addr), "r"(bytes) : "memory")
__device__ __forceinline__ void mbar_wait(u32 addr, u32 parity) {
    asm volatile(
        "{\n\t.reg .pred P;\n\t"
        "W%=:\n\t"
        "mbarrier.try_wait.parity.acquire.cta.shared::cta.b64 P, [%0], %1, 0x989680;\n\t"
        "@P bra D%=;\n\t"
        "bra W%=;\n\t"
        "D%=:\n\t}"
        :: "r"(addr), "r"(parity) : "memory");
}
#define SWZ(off) ((u32)(off) ^ ((((u32)(off)) >> 3) & 0x70))

// ───────── fp32 → fp16 hi/lo split ─────────
__global__ __launch_bounds__(256) void split16(
    const float* __restrict__ s, __half* __restrict__ h,
    __half* __restrict__ l, int n4)
{
    int i = blockIdx.x * blockDim.x + threadIdx.x;
    if (i >= n4) return;
    float4 v = ((const float4*)s)[i];
    float f[4] = {v.x, v.y, v.z, v.w};
    ushort4 ho, lo;
    unsigned short* hp = &ho.x; unsigned short* lp = &lo.x;
    #pragma unroll
    for (int j = 0; j < 4; j++) {
        __half hb = __float2half_rn(f[j]);
        __half lb = __float2half_rn(f[j] - __half2float(hb));
        hp[j] = __half_as_ushort(hb);
        lp[j] = __half_as_ushort(lb);
    }
    ((ushort4*)h)[i] = ho;
    ((ushort4*)l)[i] = lo;
}

__global__ __launch_bounds__(256) void conv16(
    const float* __restrict__ s, __half* __restrict__ h, int n4)
{
    int i = blockIdx.x * blockDim.x + threadIdx.x;
    if (i >= n4) return;
    float4 v = ((const float4*)s)[i];
    ushort4 ho;
    ho.x = __half_as_ushort(__float2half_rn(v.x));
    ho.y = __half_as_ushort(__float2half_rn(v.y));
    ho.z = __half_as_ushort(__float2half_rn(v.z));
    ho.w = __half_as_ushort(__float2half_rn(v.w));
    ((ushort4*)h)[i] = ho;
}

__global__ __launch_bounds__(256) void bias_concat(
    const float* __restrict__ bq, const float* __restrict__ bk,
    const float* __restrict__ bv, float* __restrict__ dst)
{
    int i = blockIdx.x * blockDim.x + threadIdx.x;
    if (i >= NQKV) return;
    float v;
    if (i < 4096)      v = bq[i];
    else if (i < 5120) v = bk[i - 4096];
    else               v = bv[i - 5120];
    dst[i] = v;
}

// ═════════ 1-PASS fp16 GEMM, 4-stage TMA; OUT16 picks fp16/fp32 output ═════════
#define CHK 64
#define S1_A 0u
#define S1_B 16384u
#define STB1 49152u
#define S1_CTRL (4u*STB1)
#define GSMEM1 (4*49152 + 64)

template<int OUT16>
__global__ __launch_bounds__(256, 1) void hgemm1(
    const __grid_constant__ CUtensorMap tA,
    const __grid_constant__ CUtensorMap tB,
    const float* __restrict__ bias, void* __restrict__ Cv,
    int N_, int K, int ny0)
{
    extern __shared__ __align__(1024) char smem[];
    const u32 sb   = smem_u32(smem);
    const int tid  = threadIdx.x;
    const int wid  = tid >> 5;
    const int lane = tid & 31;
    const int m0   = blockIdx.y * 128;
    const int n0   = blockIdx.x * 256;
    const int wm   = (wid & 1) * 64;
    const int wn   = (wid >> 1) * 64;
    const int nch  = K / CHK;

    float acc[4][8][4];
    #pragma unroll
    for (int i = 0; i < 4; i++)
        #pragma unroll
        for (int j = 0; j < 8; j++)
            #pragma unroll
            for (int t = 0; t < 4; t++) acc[i][j][t] = 0.f;

    if (tid == 0) {
        #pragma unroll
        for (int s = 0; s < 4; s++) MBAR_INIT(sb + S1_CTRL + s * 8, 1);
    }
    __syncthreads();

    auto issue = [&](int c) {
        if (tid == 0) {
            const int st   = c & 3;
            const u32 mbar = sb + S1_CTRL + st * 8;
            const u32 s0   = sb + st * STB1;
            MBAR_EXPECT(mbar, 49152u);
            int kc = c * CHK;
            tma2d(s0 + S1_A, &tA, kc, m0, mbar);
            tma2d(s0 + S1_B, &tB, kc, ny0 + n0, mbar);
        }
    };

    issue(0); issue(1); issue(2); issue(3);

    for (int c = 0; c < nch; c++) {
        const int st = c & 3;
        mbar_wait(sb + S1_CTRL + st * 8, (c >> 2) & 1);
        const u32 s0 = sb + st * STB1;

        #pragma unroll
        for (int ks = 0; ks < 4; ks++) {
            const int k0 = ks * 16;
            u32 a[4][4], b[4][4];
            #pragma unroll
            for (int ma = 0; ma < 4; ma++) {
                int row  = wm + ma * 16 + ((lane >> 3) & 1) * 8 + (lane & 7);
                int colB = (k0 + (lane >> 4) * 8) * 2;
                ldsm4(s0 + S1_A + SWZ(row * 128 + colB), a[ma]);
            }
            #pragma unroll
            for (int j = 0; j < 4; j++) {
                int row  = wn + j * 16 + (lane >> 4) * 8 + (lane & 7);
                int colB = (k0 + ((lane >> 3) & 1) * 8) * 2;
                ldsm4(s0 + S1_B + SWZ(row * 128 + colB), b[j]);
            }
            #pragma unroll
            for (int j = 0; j < 4; j++)
                #pragma unroll
                for (int ma = 0; ma < 4; ma++) {
                    mma16816(acc[ma][j*2+0], a[ma], &b[j][0]);
                    mma16816(acc[ma][j*2+1], a[ma], &b[j][2]);
                }
        }
        __syncthreads();
        if (c + 4 < nch) issue(c + 4);
    }

    #pragma unroll
    for (int ma = 0; ma < 4; ma++) {
        #pragma unroll
        for (int nb = 0; nb < 8; nb++) {
            int row = m0 + wm + ma * 16 + (lane >> 2);
            int col = n0 + wn + nb * 8 + (lane & 3) * 2;
            float b0 = bias[col], b1 = bias[col + 1];
            float v00 = acc[ma][nb][0] + b0, v01 = acc[ma][nb][1] + b1;
            float v10 = acc[ma][nb][2] + b0, v11 = acc[ma][nb][3] + b1;
            if (OUT16) {
                __half* C = (__half*)Cv;
                *(__half2*)(C + (size_t)row * N_ + col)       = __floats2half2_rn(v00, v01);
                *(__half2*)(C + (size_t)(row + 8) * N_ + col) = __floats2half2_rn(v10, v11);
            } else {
                float* C = (float*)Cv;
                *(float2*)(C + (size_t)row * N_ + col)       = make_float2(v00, v01);
                *(float2*)(C + (size_t)(row + 8) * N_ + col) = make_float2(v10, v11);
            }
        }
    }
}

// ═════════ 2-PASS split-x fp16 GEMM (V path): 3-stage TMA, fp32 out ═════════
#define SOFF_AH 0u
#define SOFF_AL 16384u
#define SOFF_B  32768u
#define STB 65536u
#define SM_CTRL (3u*STB)
#define GSMEM (3*65536 + 64)

__global__ __launch_bounds__(256, 1) void hgemm2(
    const __grid_constant__ CUtensorMap tAh,
    const __grid_constant__ CUtensorMap tAl,
    const __grid_constant__ CUtensorMap tB,
    const float* __restrict__ bias, float* __restrict__ C,
    int N_, int K, int ny0)
{
    extern __shared__ __align__(1024) char smem[];
    const u32 sb   = smem_u32(smem);
    const int tid  = threadIdx.x;
    const int wid  = tid >> 5;
    const int lane = tid & 31;
    const int m0   = blockIdx.y * 128;
    const int n0   = blockIdx.x * 256;
    const int wm   = (wid & 1) * 64;
    const int wn   = (wid >> 1) * 64;
    const int nch  = K / CHK;

    float acc[4][8][4];
    #pragma unroll
    for (int i = 0; i < 4; i++)
        #pragma unroll
        for (int j = 0; j < 8; j++)
            #pragma unroll
            for (int t = 0; t < 4; t++) acc[i][j][t] = 0.f;

    if (tid == 0) {
        MBAR_INIT(sb + SM_CTRL, 1);
        MBAR_INIT(sb + SM_CTRL + 8, 1);
        MBAR_INIT(sb + SM_CTRL + 16, 1);
    }
    __syncthreads();

    auto issue = [&](int c) {
        if (tid == 0) {
            const int st   = c % 3;
            const u32 mbar = sb + SM_CTRL + st * 8;
            const u32 s0   = sb + st * STB;
            MBAR_EXPECT(mbar, 65536u);
            int kc = c * CHK;
            tma2d(s0 + SOFF_AH, &tAh, kc, m0, mbar);
            tma2d(s0 + SOFF_AL, &tAl, kc, m0, mbar);
            tma2d(s0 + SOFF_B,  &tB,  kc, ny0 + n0, mbar);
        }
    };

    issue(0); issue(1); issue(2);

    for (int c = 0; c < nch; c++) {
        const int st = c % 3;
        mbar_wait(sb + SM_CTRL + st * 8, (c / 3) & 1);
        const u32 s0 = sb + st * STB;

        #pragma unroll
        for (int ks = 0; ks < 4; ks++) {
            const int k0 = ks * 16;
            u32 ah[4][4], al[4][4], b[4][4];
            #pragma unroll
            for (int ma = 0; ma < 4; ma++) {
                int row  = wm + ma * 16 + ((lane >> 3) & 1) * 8 + (lane & 7);
                int colB = (k0 + (lane >> 4) * 8) * 2;
                u32 off  = SWZ(row * 128 + colB);
                ldsm4(s0 + SOFF_AH + off, ah[ma]);
                ldsm4(s0 + SOFF_AL + off, al[ma]);
            }
            #pragma unroll
            for (int j = 0; j < 4; j++) {
                int row  = wn + j * 16 + (lane >> 4) * 8 + (lane & 7);
                int colB = (k0 + ((lane >> 3) & 1) * 8) * 2;
                ldsm4(s0 + SOFF_B + SWZ(row * 128 + colB), b[j]);
            }
            #pragma unroll
            for (int j = 0; j < 4; j++)
                #pragma unroll
                for (int ma = 0; ma < 4; ma++) {
                    mma16816(acc[ma][j*2+0], ah[ma], &b[j][0]);
                    mma16816(acc[ma][j*2+1], ah[ma], &b[j][2]);
                }
            #pragma unroll
            for (int j = 0; j < 4; j++)
                #pragma unroll
                for (int ma = 0; ma < 4; ma++) {
                    mma16816(acc[ma][j*2+0], al[ma], &b[j][0]);
                    mma16816(acc[ma][j*2+1], al[ma], &b[j][2]);
                }
        }
        __syncthreads();
        if (c + 3 < nch) issue(c + 3);
    }

    #pragma unroll
    for (int ma = 0; ma < 4; ma++) {
        #pragma unroll
        for (int nb = 0; nb < 8; nb++) {
            int row = m0 + wm + ma * 16 + (lane >> 2);
            int col = n0 + wn + nb * 8 + (lane & 3) * 2;
            float b0 = bias[col], b1 = bias[col + 1];
            float* p = C + (size_t)row * N_ + col;
            *(float2*)p = make_float2(acc[ma][nb][0] + b0, acc[ma][nb][1] + b1);
            *(float2*)(p + 8 * (size_t)N_) =
                make_float2(acc[ma][nb][2] + b0, acc[ma][nb][3] + b1);
        }
    }
}

// ───────── per-token attention: fp16 q|k in, fp32 v in, fp16 z out ─────────
__global__ __launch_bounds__(256) void attn_kernel(
    const __half* __restrict__ qk, const float* __restrict__ v,
    __half* __restrict__ z)
{
    __shared__ float sk[HH][66];
    __shared__ float sv[HH][66];
    __shared__ float sq[QQ][HH][66];
    __shared__ float ss[QQ*HH][HH + 1];
    __shared__ float sp_[QQ*HH][HH + 1];

    const int n   = blockIdx.x;
    const int b   = n >> 11;
    const int sp  = n & 2047;
    const int tid = threadIdx.x;

    {
        // q: 4096 halfs = 512 uint4; k: 1024 halfs = 128 uint4; v: 256 float4
        const uint4* q4 = (const uint4*)(qk + (size_t)n * NQK);
        #pragma unroll
        for (int j = 0; j < 2; j++) {
            int idx = tid + j * 256;
            uint4 u = q4[idx];
            const __half2* h2 = (const __half2*)&u;
            int qi = idx >> 7, off = (idx & 127) * 8;
            int rr = off >> 6, cc = off & 63;
            #pragma unroll
            for (int t = 0; t < 4; t++) {
                float2 f = __half22float2(h2[t]);
                sq[qi][rr][cc + t*2]     = f.x;
                sq[qi][rr][cc + t*2 + 1] = f.y;
            }
        }
        if (tid < 128) {
            uint4 u = q4[512 + tid];                  // k at halfs [4096,5120)
            const __half2* h2 = (const __half2*)&u;
            int rr = tid >> 3, cc = (tid & 7) * 8;
            #pragma unroll
            for (int t = 0; t < 4; t++) {
                float2 f = __half22float2(h2[t]);
                sk[rr][cc + t*2]     = f.x;
                sk[rr][cc + t*2 + 1] = f.y;
            }
        }
        const float4* v4 = (const float4*)(v + (size_t)n * EE);
        int r = tid >> 4, c4 = (tid & 15) * 4;
        float4 vf = v4[tid];
        sv[r][c4] = vf.x; sv[r][c4+1] = vf.y; sv[r][c4+2] = vf.z; sv[r][c4+3] = vf.w;
    }
    __syncthreads();

    {
        const int h = tid >> 4, g = tid & 15;
        const float2* kr = (const float2*)&sk[g][0];
        #pragma unroll
        for (int qi = 0; qi < QQ; qi++) {
            const float2* qr = (const float2*)&sq[qi][h][0];
            float s = 0.f;
            #pragma unroll
            for (int dd = 0; dd < 32; dd++) {
                float2 a = qr[dd], c = kr[dd];
                s += a.x * c.x + a.y * c.y;
            }
            ss[qi * HH + h][g] = s * 0.125f;
        }
    }
    __syncthreads();

    if (tid < QQ * HH) {
        float m = -1e30f;
        #pragma unroll
        for (int g = 0; g < HH; g++) m = fmaxf(m, ss[tid][g]);
        float e[HH], sum = 0.f;
        #pragma unroll
        for (int g = 0; g < HH; g++) { e[g] = __expf(ss[tid][g] - m); sum += e[g]; }
        float inv = 1.f / sum;
        #pragma unroll
        for (int g = 0; g < HH; g++) sp_[tid][g] = e[g] * inv;
    }
    __syncthreads();

    const int d  = tid & 63;
    const int hq = tid >> 6;
    #pragma unroll
    for (int j = 0; j < 4; j++) {
        int h = hq * 4 + j;
        float o = 0.f;
        #pragma unroll
        for (int qi = 0; qi < QQ; qi++) {
            const float* pr = sp_[qi * HH + h];
            #pragma unroll
            for (int g = 0; g < HH; g++) o += pr[g] * sv[g][d];
        }
        int sfin = h * 128 + (sp >> 4);
        int e    = ((sp & 15) << 6) + d;
        z[((size_t)b * SS + sfin) * EE + e] = __float2half_rn(o);
    }
}

// ───────── host ─────────
typedef CUresult (*PFN_encode)(
    CUtensorMap*, CUtensorMapDataType, cuuint32_t, void*,
    const cuuint64_t*, const cuuint64_t*, const cuuint32_t*, const cuuint32_t*,
    CUtensorMapInterleave, CUtensorMapSwizzle, CUtensorMapL2promotion,
    CUtensorMapFloatOOBfill);

static CUtensorMap mk_map16(PFN_encode enc, void* base, u64 rows, u32 boxrows) {
    CUtensorMap m;
    cuuint64_t dims[2]    = {(cuuint64_t)EE, rows};
    cuuint64_t strides[1] = {(cuuint64_t)EE * 2};
    cuuint32_t box[2]     = {64u, boxrows};
    cuuint32_t es[2]      = {1u, 1u};
    enc(&m, CU_TENSOR_MAP_DATA_TYPE_FLOAT16, 2, base, dims, strides, box, es,
        CU_TENSOR_MAP_INTERLEAVE_NONE, CU_TENSOR_MAP_SWIZZLE_128B,
        CU_TENSOR_MAP_L2_PROMOTION_L2_128B, CU_TENSOR_MAP_FLOAT_OOB_FILL_NONE);
    return m;
}

extern "C" void kernel_launch(void* const* d_in, const int* in_sizes, int n_in,
                              void* d_out, int out_size)
{
    const float* x  = (const float*)d_in[0];
    const float* Wq = (const float*)d_in[1];
    const float* bq = (const float*)d_in[2];
    const float* Wk = (const float*)d_in[3];
    const float* bk = (const float*)d_in[4];
    const float* Wv = (const float*)d_in[5];
    const float* bv = (const float*)d_in[6];
    const float* Wo = (const float*)d_in[7];
    const float* bo = (const float*)d_in[8];
    float* out = (float*)d_out;

    float *pv, *pbqkv;
    __half *pqk, *pz, *xh, *xl, *wqkv, *wo;
    cudaGetSymbolAddress((void**)&pqk,  g_qk);
    cudaGetSymbolAddress((void**)&pv,   g_v);
    cudaGetSymbolAddress((void**)&pz,   g_z);
    cudaGetSymbolAddress((void**)&pbqkv, g_bqkv);
    cudaGetSymbolAddress((void**)&xh, g_xh);  cudaGetSymbolAddress((void**)&xl, g_xl);
    cudaGetSymbolAddress((void**)&wqkv, g_wqkv);
    cudaGetSymbolAddress((void**)&wo, g_wo);

    PFN_encode enc = 0;
    cudaDriverEntryPointQueryResult qr;
    cudaGetDriverEntryPoint("cuTensorMapEncodeTiled", (void**)&enc,
                            cudaEnableDefault, &qr);

    CUtensorMap mXh = mk_map16(enc, xh, MM, 128);
    CUtensorMap mXl = mk_map16(enc, xl, MM, 128);
    CUtensorMap mZ  = mk_map16(enc, pz, MM, 128);
    CUtensorMap mW  = mk_map16(enc, wqkv, NQKV, 256);
    CUtensorMap mO  = mk_map16(enc, wo, EE, 256);

    cudaFuncSetAttribute(hgemm1<1>, cudaFuncAttributeMaxDynamicSharedMemorySize, GSMEM1);
    cudaFuncSetAttribute(hgemm1<0>, cudaFuncAttributeMaxDynamicSharedMemorySize, GSMEM1);
    cudaFuncSetAttribute(hgemm2,    cudaFuncAttributeMaxDynamicSharedMemorySize, GSMEM);

    dim3 blk(256);
    split16<<<(MM*EE/4 + 255)/256, blk>>>(x, xh, xl, MM*EE/4);
    conv16<<<(QQ*EE*EE/4 + 255)/256, blk>>>(Wq, wqkv,                QQ*EE*EE/4);
    conv16<<<(EE*EE/4 + 255)/256, blk>>>(Wk, wqkv + (size_t)4096*EE, EE*EE/4);
    conv16<<<(EE*EE/4 + 255)/256, blk>>>(Wv, wqkv + (size_t)5120*EE, EE*EE/4);
    conv16<<<(EE*EE/4 + 255)/256, blk>>>(Wo, wo,                     EE*EE/4);
    bias_concat<<<(NQKV + 255)/256, blk>>>(bq, bk, bv, pbqkv);

    // Q|K: 1-pass, fp16 output (score path — error-attenuated)
    hgemm1<1><<<dim3(NQK/256, MM/128), blk, GSMEM1>>>(
        mXh, mW, pbqkv, pqk, NQK, EE, 0);
    // V: 2-pass split-x, fp32 output (direct path — protected)
    hgemm2<<<dim3(EE/256, MM/128), blk, GSMEM>>>(
        mXh, mXl, mW, pbqkv + NQK, pv, EE, EE, NQK);

    attn_kernel<<<MM, blk>>>(pqk, pv, pz);

    // O: 1-pass on fp16 z (adds one direct rounding term — budgeted)
    hgemm1<0><<<dim3(EE/256, MM/128), blk, GSMEM1>>>(
        mZ, mO, bo, out, EE, EE, 0);
}

// round 12
// speedup vs baseline: 1.5065x; 1.1037x over previous
#include <cuda_runtime.h>
#include <cuda.h>
#include <cuda_fp16.h>

typedef unsigned int u32;
typedef unsigned long long u64;

#define BB 4
#define SS 2048
#define EE 1024
#define HH 16
#define DD 64
#define QQ 4
#define MM (BB*SS)     /* 8192 tokens */
#define NQKV 6144
#define NQK  5120      /* q|k fp16 1-pass class */

// ───────── scratch (allocation-free rule: __device__ globals) ─────────
__device__ __half g_qk[(size_t)MM * NQK];      // q|k projection, fp16
__device__ float  g_v [(size_t)MM * EE];       // v projection, fp32 out
__device__ __half g_z [(size_t)MM * EE];       // attn output, fp16
__device__ float  g_bqkv[NQKV];

__device__ __half g_xh[(size_t)MM*EE];         // x in fp16
__device__ __half g_wqkv[(size_t)NQKV*EE];     // Wq|Wk|Wv fp16
__device__ __half g_wo[(size_t)EE*EE];

__device__ __forceinline__ u32 smem_u32(const void* p) {
    u32 a;
    asm("{ .reg .u64 t; cvta.to.shared.u64 t, %1; cvt.u32.u64 %0, t; }"
        : "=r"(a) : "l"(p));
    return a;
}
__device__ __forceinline__ void ldsm4(u32 addr, u32* r) {
    asm volatile("ldmatrix.sync.aligned.m8n8.x4.shared.b16 {%0,%1,%2,%3}, [%4];"
                 : "=r"(r[0]), "=r"(r[1]), "=r"(r[2]), "=r"(r[3]) : "r"(addr));
}
__device__ __forceinline__ void mma16816(float* c, const u32* a, const u32* b) {
    asm volatile(
        "mma.sync.aligned.m16n8k16.row.col.f32.f16.f16.f32 "
        "{%0,%1,%2,%3}, {%4,%5,%6,%7}, {%8,%9}, {%0,%1,%2,%3};"
        : "+f"(c[0]), "+f"(c[1]), "+f"(c[2]), "+f"(c[3])
        : "r"(a[0]), "r"(a[1]), "r"(a[2]), "r"(a[3]), "r"(b[0]), "r"(b[1]));
}
__device__ __forceinline__ void tma2d(u32 saddr, const CUtensorMap* m,
                                      int cx, int cy, u32 mbar) {
    asm volatile(
        "cp.async.bulk.tensor.2d.shared::cta.global.tile.mbarrier::complete_tx::bytes "
        "[%0], [%1, {%2, %3}], [%4];"
        :: "r"(saddr), "l"(m), "r"(cx), "r"(cy), "r"(mbar) : "memory");
}
#define MBAR_INIT(addr, cnt) \
    asm volatile("mbarrier.init.shared.b64 [%0], %1;" :: "r"(addr), "r"(cnt) : "memory")
#define MBAR_EXPECT(addr, bytes) \
    asm volatile("mbarrier.arrive.expect_tx.shared.b64 _, [%0], %1;" \
                 :: "r"(addr), "r"(bytes) : "memory")
__device__ __forceinline__ void mbar_wait(u32 addr, u32 parity) {
    asm volatile(
        "{\n\t.reg .pred P;\n\t"
        "W%=:\n\t"
        "mbarrier.try_wait.parity.acquire.cta.shared::cta.b64 P, [%0], %1, 0x989680;\n\t"
        "@P bra D%=;\n\t"
        "bra W%=;\n\t"
        "D%=:\n\t}"
        :: "r"(addr), "r"(parity) : "memory");
}
#define SWZ(off) ((u32)(off) ^ ((((u32)(off)) >> 3) & 0x70))

// ───────── fp32 → fp16 ─────────
__global__ __launch_bounds__(256) void conv16(
    const float* __restrict__ s, __half* __restrict__ h, int n4)
{
    int i = blockIdx.x * blockDim.x + threadIdx.x;
    if (i >= n4) return;
    float4 v = ((const float4*)s)[i];
    ushort4 ho;
    ho.x = __half_as_ushort(__float2half_rn(v.x));
    ho.y = __half_as_ushort(__float2half_rn(v.y));
    ho.z = __half_as_ushort(__float2half_rn(v.z));
    ho.w = __half_as_ushort(__float2half_rn(v.w));
    ((ushort4*)h)[i] = ho;
}

__global__ __launch_bounds__(256) void bias_concat(
    const float* __restrict__ bq, const float* __restrict__ bk,
    const float* __restrict__ bv, float* __restrict__ dst)
{
    int i = blockIdx.x * blockDim.x + threadIdx.x;
    if (i >= NQKV) return;
    float v;
    if (i < 4096)      v = bq[i];
    else if (i < 5120) v = bk[i - 4096];
    else               v = bv[i - 5120];
    dst[i] = v;
}

// ═════════ 1-PASS fp16 GEMM, 4-stage TMA; OUT16 picks fp16/fp32 output ═════════
#define CHK 64
#define S1_A 0u
#define S1_B 16384u
#define STB1 49152u
#define S1_CTRL (4u*STB1)
#define GSMEM1 (4*49152 + 64)

template<int OUT16>
__global__ __launch_bounds__(256, 1) void hgemm1(
    const __grid_constant__ CUtensorMap tA,
    const __grid_constant__ CUtensorMap tB,
    const float* __restrict__ bias, void* __restrict__ Cv,
    int N_, int K, int ny0)
{
    extern __shared__ __align__(1024) char smem[];
    const u32 sb   = smem_u32(smem);
    const int tid  = threadIdx.x;
    const int wid  = tid >> 5;
    const int lane = tid & 31;
    const int m0   = blockIdx.y * 128;
    const int n0   = blockIdx.x * 256;
    const int wm   = (wid & 1) * 64;
    const int wn   = (wid >> 1) * 64;
    const int nch  = K / CHK;

    float acc[4][8][4];
    #pragma unroll
    for (int i = 0; i < 4; i++)
        #pragma unroll
        for (int j = 0; j < 8; j++)
            #pragma unroll
            for (int t = 0; t < 4; t++) acc[i][j][t] = 0.f;

    if (tid == 0) {
        #pragma unroll
        for (int s = 0; s < 4; s++) MBAR_INIT(sb + S1_CTRL + s * 8, 1);
    }
    __syncthreads();

    auto issue = [&](int c) {
        if (tid == 0) {
            const int st   = c & 3;
            const u32 mbar = sb + S1_CTRL + st * 8;
            const u32 s0   = sb + st * STB1;
            MBAR_EXPECT(mbar, 49152u);
            int kc = c * CHK;
            tma2d(s0 + S1_A, &tA, kc, m0, mbar);
            tma2d(s0 + S1_B, &tB, kc, ny0 + n0, mbar);
        }
    };

    issue(0); issue(1); issue(2); issue(3);

    for (int c = 0; c < nch; c++) {
        const int st = c & 3;
        mbar_wait(sb + S1_CTRL + st * 8, (c >> 2) & 1);
        const u32 s0 = sb + st * STB1;

        #pragma unroll
        for (int ks = 0; ks < 4; ks++) {
            const int k0 = ks * 16;
            u32 a[4][4], b[4][4];
            #pragma unroll
            for (int ma = 0; ma < 4; ma++) {
                int row  = wm + ma * 16 + ((lane >> 3) & 1) * 8 + (lane & 7);
                int colB = (k0 + (lane >> 4) * 8) * 2;
                ldsm4(s0 + S1_A + SWZ(row * 128 + colB), a[ma]);
            }
            #pragma unroll
            for (int j = 0; j < 4; j++) {
                int row  = wn + j * 16 + (lane >> 4) * 8 + (lane & 7);
                int colB = (k0 + ((lane >> 3) & 1) * 8) * 2;
                ldsm4(s0 + S1_B + SWZ(row * 128 + colB), b[j]);
            }
            #pragma unroll
            for (int j = 0; j < 4; j++)
                #pragma unroll
                for (int ma = 0; ma < 4; ma++) {
                    mma16816(acc[ma][j*2+0], a[ma], &b[j][0]);
                    mma16816(acc[ma][j*2+1], a[ma], &b[j][2]);
                }
        }
        __syncthreads();
        if (c + 4 < nch) issue(c + 4);
    }

    #pragma unroll
    for (int ma = 0; ma < 4; ma++) {
        #pragma unroll
        for (int nb = 0; nb < 8; nb++) {
            int row = m0 + wm + ma * 16 + (lane >> 2);
            int col = n0 + wn + nb * 8 + (lane & 3) * 2;
            float b0 = bias[col], b1 = bias[col + 1];
            float v00 = acc[ma][nb][0] + b0, v01 = acc[ma][nb][1] + b1;
            float v10 = acc[ma][nb][2] + b0, v11 = acc[ma][nb][3] + b1;
            if (OUT16) {
                __half* C = (__half*)Cv;
                *(__half2*)(C + (size_t)row * N_ + col)       = __floats2half2_rn(v00, v01);
                *(__half2*)(C + (size_t)(row + 8) * N_ + col) = __floats2half2_rn(v10, v11);
            } else {
                float* C = (float*)Cv;
                *(float2*)(C + (size_t)row * N_ + col)       = make_float2(v00, v01);
                *(float2*)(C + (size_t)(row + 8) * N_ + col) = make_float2(v10, v11);
            }
        }
    }
}

// ───────── per-token attention v2: fp16 smem staging + shuffle softmax ─────────
// Phases: load → sync → scores+softmax (shfl reductions, no barrier) → sync → P·V.
__global__ __launch_bounds__(256) void attn_kernel(
    const __half* __restrict__ qk, const float* __restrict__ v,
    __half* __restrict__ z)
{
    __shared__ __half2 sq2[QQ][HH][34];
    __shared__ __half2 sk2[HH][34];
    __shared__ float   sv[HH][66];
    __shared__ float   sp_[QQ*HH][HH + 1];

    const int n   = blockIdx.x;
    const int b   = n >> 11;
    const int sp  = n & 2047;
    const int tid = threadIdx.x;

    // ── load: q 512 uint4, k 128 uint4 (fp16 as-is), v 256 float4 ──
    {
        const uint4* q4 = (const uint4*)(qk + (size_t)n * NQK);
        #pragma unroll
        for (int j = 0; j < 2; j++) {
            int idx = tid + j * 256;
            uint4 u = q4[idx];
            const __half2* h2 = (const __half2*)&u;
            int qi = idx >> 7, rr = (idx >> 3) & 15, cc = (idx & 7) * 4;
            #pragma unroll
            for (int t = 0; t < 4; t++) sq2[qi][rr][cc + t] = h2[t];
        }
        if (tid < 128) {
            uint4 u = q4[512 + tid];
            const __half2* h2 = (const __half2*)&u;
            int rr = tid >> 3, cc = (tid & 7) * 4;
            #pragma unroll
            for (int t = 0; t < 4; t++) sk2[rr][cc + t] = h2[t];
        }
        const float4* v4 = (const float4*)(v + (size_t)n * EE);
        int r = tid >> 4, c4 = (tid & 15) * 4;
        float4 vf = v4[tid];
        sv[r][c4] = vf.x; sv[r][c4+1] = vf.y; sv[r][c4+2] = vf.z; sv[r][c4+3] = vf.w;
    }
    __syncthreads();

    // ── scores + fused softmax: thread (h = tid>>4, g = tid&15) ──
    {
        const int h = tid >> 4, g = tid & 15;
        #pragma unroll
        for (int qi = 0; qi < QQ; qi++) {
            float s = 0.f;
            #pragma unroll
            for (int dd = 0; dd < 32; dd++) {
                float2 a = __half22float2(sq2[qi][h][dd]);
                float2 c = __half22float2(sk2[g][dd]);
                s += a.x * c.x + a.y * c.y;
            }
            s *= 0.125f;
            // 16-lane reductions (xor<16 stays inside the g-group)
            float m = s;
            #pragma unroll
            for (int o = 8; o; o >>= 1) m = fmaxf(m, __shfl_xor_sync(~0u, m, o));
            float e = __expf(s - m);
            float sum = e;
            #pragma unroll
            for (int o = 8; o; o >>= 1) sum += __shfl_xor_sync(~0u, sum, o);
            sp_[qi * HH + h][g] = e / sum;
        }
    }
    __syncthreads();

    // ── P·V summed over qi; shuffled fp16 write ──
    const int d  = tid & 63;
    const int hq = tid >> 6;
    #pragma unroll
    for (int j = 0; j < 4; j++) {
        int h = hq * 4 + j;
        float o = 0.f;
        #pragma unroll
        for (int qi = 0; qi < QQ; qi++) {
            const float* pr = sp_[qi * HH + h];
            #pragma unroll
            for (int g = 0; g < HH; g++) o += pr[g] * sv[g][d];
        }
        int sfin = h * 128 + (sp >> 4);
        int e    = ((sp & 15) << 6) + d;
        z[((size_t)b * SS + sfin) * EE + e] = __float2half_rn(o);
    }
}

// ───────── host ─────────
typedef CUresult (*PFN_encode)(
    CUtensorMap*, CUtensorMapDataType, cuuint32_t, void*,
    const cuuint64_t*, const cuuint64_t*, const cuuint32_t*, const cuuint32_t*,
    CUtensorMapInterleave, CUtensorMapSwizzle, CUtensorMapL2promotion,
    CUtensorMapFloatOOBfill);

static CUtensorMap mk_map16(PFN_encode enc, void* base, u64 rows, u32 boxrows) {
    CUtensorMap m;
    cuuint64_t dims[2]    = {(cuuint64_t)EE, rows};
    cuuint64_t strides[1] = {(cuuint64_t)EE * 2};
    cuuint32_t box[2]     = {64u, boxrows};
    cuuint32_t es[2]      = {1u, 1u};
    enc(&m, CU_TENSOR_MAP_DATA_TYPE_FLOAT16, 2, base, dims, strides, box, es,
        CU_TENSOR_MAP_INTERLEAVE_NONE, CU_TENSOR_MAP_SWIZZLE_128B,
        CU_TENSOR_MAP_L2_PROMOTION_L2_128B, CU_TENSOR_MAP_FLOAT_OOB_FILL_NONE);
    return m;
}

extern "C" void kernel_launch(void* const* d_in, const int* in_sizes, int n_in,
                              void* d_out, int out_size)
{
    const float* x  = (const float*)d_in[0];
    const float* Wq = (const float*)d_in[1];
    const float* bq = (const float*)d_in[2];
    const float* Wk = (const float*)d_in[3];
    const float* bk = (const float*)d_in[4];
    const float* Wv = (const float*)d_in[5];
    const float* bv = (const float*)d_in[6];
    const float* Wo = (const float*)d_in[7];
    const float* bo = (const float*)d_in[8];
    float* out = (float*)d_out;

    float *pv, *pbqkv;
    __half *pqk, *pz, *xh, *wqkv, *wo;
    cudaGetSymbolAddress((void**)&pqk,  g_qk);
    cudaGetSymbolAddress((void**)&pv,   g_v);
    cudaGetSymbolAddress((void**)&pz,   g_z);
    cudaGetSymbolAddress((void**)&pbqkv, g_bqkv);
    cudaGetSymbolAddress((void**)&xh, g_xh);
    cudaGetSymbolAddress((void**)&wqkv, g_wqkv);
    cudaGetSymbolAddress((void**)&wo, g_wo);

    PFN_encode enc = 0;
    cudaDriverEntryPointQueryResult qr;
    cudaGetDriverEntryPoint("cuTensorMapEncodeTiled", (void**)&enc,
                            cudaEnableDefault, &qr);

    CUtensorMap mXh = mk_map16(enc, xh, MM, 128);
    CUtensorMap mZ  = mk_map16(enc, pz, MM, 128);
    CUtensorMap mW  = mk_map16(enc, wqkv, NQKV, 256);
    CUtensorMap mO  = mk_map16(enc, wo, EE, 256);

    cudaFuncSetAttribute(hgemm1<1>, cudaFuncAttributeMaxDynamicSharedMemorySize, GSMEM1);
    cudaFuncSetAttribute(hgemm1<0>, cudaFuncAttributeMaxDynamicSharedMemorySize, GSMEM1);

    dim3 blk(256);
    conv16<<<(MM*EE/4 + 255)/256, blk>>>(x, xh, MM*EE/4);
    conv16<<<(QQ*EE*EE/4 + 255)/256, blk>>>(Wq, wqkv,                QQ*EE*EE/4);
    conv16<<<(EE*EE/4 + 255)/256, blk>>>(Wk, wqkv + (size_t)4096*EE, EE*EE/4);
    conv16<<<(EE*EE/4 + 255)/256, blk>>>(Wv, wqkv + (size_t)5120*EE, EE*EE/4);
    conv16<<<(EE*EE/4 + 255)/256, blk>>>(Wo, wo,                     EE*EE/4);
    bias_concat<<<(NQKV + 255)/256, blk>>>(bq, bk, bv, pbqkv);

    // Q|K: 1-pass, fp16 out (score path — error-attenuated)
    hgemm1<1><<<dim3(NQK/256, MM/128), blk, GSMEM1>>>(
        mXh, mW, pbqkv, pqk, NQK, EE, 0);
    // V: 1-pass, fp32 out (direct path; x-rounding term budgeted)
    hgemm1<0><<<dim3(EE/256, MM/128), blk, GSMEM1>>>(
        mXh, mW, pbqkv + NQK, pv, EE, EE, NQK);

    attn_kernel<<<MM, blk>>>(pqk, pv, pz);

    // O: 1-pass on fp16 z
    hgemm1<0><<<dim3(EE/256, MM/128), blk, GSMEM1>>>(
        mZ, mO, bo, out, EE, EE, 0);
}

// round 13
// speedup vs baseline: 1.6117x; 1.0698x over previous
#include <cuda_runtime.h>
#include <cuda.h>
#include <cuda_fp16.h>

typedef unsigned int u32;
typedef unsigned long long u64;

#define BB 4
#define SS 2048
#define EE 1024
#define HH 16
#define DD 64
#define QQ 4
#define MM (BB*SS)     /* 8192 tokens */
#define NQKV 6144
#define NQK  5120      /* q|k fp16 1-pass class */

// ───────── scratch (allocation-free rule: __device__ globals) ─────────
__device__ __half g_qk[(size_t)MM * NQK];      // q|k projection, fp16
__device__ float  g_v [(size_t)MM * EE];       // v projection, fp32 out
__device__ __half g_z [(size_t)MM * EE];       // attn output, fp16
__device__ float  g_bqkv[NQKV];

__device__ __half g_xh[(size_t)MM*EE];         // x in fp16
__device__ __half g_wqkv[(size_t)NQKV*EE];     // Wq|Wk|Wv fp16
__device__ __half g_wo[(size_t)EE*EE];

__device__ __forceinline__ u32 smem_u32(const void* p) {
    u32 a;
    asm("{ .reg .u64 t; cvta.to.shared.u64 t, %1; cvt.u32.u64 %0, t; }"
        : "=r"(a) : "l"(p));
    return a;
}
__device__ __forceinline__ void ldsm4(u32 addr, u32* r) {
    asm volatile("ldmatrix.sync.aligned.m8n8.x4.shared.b16 {%0,%1,%2,%3}, [%4];"
                 : "=r"(r[0]), "=r"(r[1]), "=r"(r[2]), "=r"(r[3]) : "r"(addr));
}
__device__ __forceinline__ void mma16816(float* c, const u32* a, const u32* b) {
    asm volatile(
        "mma.sync.aligned.m16n8k16.row.col.f32.f16.f16.f32 "
        "{%0,%1,%2,%3}, {%4,%5,%6,%7}, {%8,%9}, {%0,%1,%2,%3};"
        : "+f"(c[0]), "+f"(c[1]), "+f"(c[2]), "+f"(c[3])
        : "r"(a[0]), "r"(a[1]), "r"(a[2]), "r"(a[3]), "r"(b[0]), "r"(b[1]));
}
__device__ __forceinline__ void tma2d(u32 saddr, const CUtensorMap* m,
                                      int cx, int cy, u32 mbar) {
    asm volatile(
        "cp.async.bulk.tensor.2d.shared::cta.global.tile.mbarrier::complete_tx::bytes "
        "[%0], [%1, {%2, %3}], [%4];"
        :: "r"(saddr), "l"(m), "r"(cx), "r"(cy), "r"(mbar) : "memory");
}
#define MBAR_INIT(addr, cnt) \
    asm volatile("mbarrier.init.shared.b64 [%0], %1;" :: "r"(addr), "r"(cnt) : "memory")
#define MBAR_EXPECT(addr, bytes) \
    asm volatile("mbarrier.arrive.expect_tx.shared.b64 _, [%0], %1;" \
                 :: "r"(addr), "r"(bytes) : "memory")
__device__ __forceinline__ void mbar_wait(u32 addr, u32 parity) {
    asm volatile(
        "{\n\t.reg .pred P;\n\t"
        "W%=:\n\t"
        "mbarrier.try_wait.parity.acquire.cta.shared::cta.b64 P, [%0], %1, 0x989680;\n\t"
        "@P bra D%=;\n\t"
        "bra W%=;\n\t"
        "D%=:\n\t}"
        :: "r"(addr), "r"(parity) : "memory");
}
#define SWZ(off) ((u32)(off) ^ ((((u32)(off)) >> 3) & 0x70))

// ───────── fp32 → fp16 ─────────
__global__ __launch_bounds__(256) void conv16(
    const float* __restrict__ s, __half* __restrict__ h, int n4)
{
    int i = blockIdx.x * blockDim.x + threadIdx.x;
    if (i >= n4) return;
    float4 v = ((const float4*)s)[i];
    ushort4 ho;
    ho.x = __half_as_ushort(__float2half_rn(v.x));
    ho.y = __half_as_ushort(__float2half_rn(v.y));
    ho.z = __half_as_ushort(__float2half_rn(v.z));
    ho.w = __half_as_ushort(__float2half_rn(v.w));
    ((ushort4*)h)[i] = ho;
}

__global__ __launch_bounds__(256) void bias_concat(
    const float* __restrict__ bq, const float* __restrict__ bk,
    const float* __restrict__ bv, float* __restrict__ dst)
{
    int i = blockIdx.x * blockDim.x + threadIdx.x;
    if (i >= NQKV) return;
    float v;
    if (i < 4096)      v = bq[i];
    else if (i < 5120) v = bk[i - 4096];
    else               v = bv[i - 5120];
    dst[i] = v;
}

// ═════════ 1-PASS fp16 GEMM, 4-stage TMA; OUT16 picks fp16/fp32 output ═════════
#define CHK 64
#define S1_A 0u
#define S1_B 16384u
#define STB1 49152u
#define S1_CTRL (4u*STB1)
#define GSMEM1 (4*49152 + 64)

template<int OUT16>
__global__ __launch_bounds__(256, 1) void hgemm1(
    const __grid_constant__ CUtensorMap tA,
    const __grid_constant__ CUtensorMap tB,
    const float* __restrict__ bias, void* __restrict__ Cv,
    int N_, int K, int ny0)
{
    extern __shared__ __align__(1024) char smem[];
    const u32 sb   = smem_u32(smem);
    const int tid  = threadIdx.x;
    const int wid  = tid >> 5;
    const int lane = tid & 31;
    const int m0   = blockIdx.y * 128;
    const int n0   = blockIdx.x * 256;
    const int wm   = (wid & 1) * 64;
    const int wn   = (wid >> 1) * 64;
    const int nch  = K / CHK;

    float acc[4][8][4];
    #pragma unroll
    for (int i = 0; i < 4; i++)
        #pragma unroll
        for (int j = 0; j < 8; j++)
            #pragma unroll
            for (int t = 0; t < 4; t++) acc[i][j][t] = 0.f;

    if (tid == 0) {
        #pragma unroll
        for (int s = 0; s < 4; s++) MBAR_INIT(sb + S1_CTRL + s * 8, 1);
    }
    __syncthreads();

    auto issue = [&](int c) {
        if (tid == 0) {
            const int st   = c & 3;
            const u32 mbar = sb + S1_CTRL + st * 8;
            const u32 s0   = sb + st * STB1;
            MBAR_EXPECT(mbar, 49152u);
            int kc = c * CHK;
            tma2d(s0 + S1_A, &tA, kc, m0, mbar);
            tma2d(s0 + S1_B, &tB, kc, ny0 + n0, mbar);
        }
    };

    issue(0); issue(1); issue(2); issue(3);

    for (int c = 0; c < nch; c++) {
        const int st = c & 3;
        mbar_wait(sb + S1_CTRL + st * 8, (c >> 2) & 1);
        const u32 s0 = sb + st * STB1;

        #pragma unroll
        for (int ks = 0; ks < 4; ks++) {
            const int k0 = ks * 16;
            u32 a[4][4], b[4][4];
            #pragma unroll
            for (int ma = 0; ma < 4; ma++) {
                int row  = wm + ma * 16 + ((lane >> 3) & 1) * 8 + (lane & 7);
                int colB = (k0 + (lane >> 4) * 8) * 2;
                ldsm4(s0 + S1_A + SWZ(row * 128 + colB), a[ma]);
            }
            #pragma unroll
            for (int j = 0; j < 4; j++) {
                int row  = wn + j * 16 + (lane >> 4) * 8 + (lane & 7);
                int colB = (k0 + ((lane >> 3) & 1) * 8) * 2;
                ldsm4(s0 + S1_B + SWZ(row * 128 + colB), b[j]);
            }
            #pragma unroll
            for (int j = 0; j < 4; j++)
                #pragma unroll
                for (int ma = 0; ma < 4; ma++) {
                    mma16816(acc[ma][j*2+0], a[ma], &b[j][0]);
                    mma16816(acc[ma][j*2+1], a[ma], &b[j][2]);
                }
        }
        __syncthreads();
        if (c + 4 < nch) issue(c + 4);
    }

    #pragma unroll
    for (int ma = 0; ma < 4; ma++) {
        #pragma unroll
        for (int nb = 0; nb < 8; nb++) {
            int row = m0 + wm + ma * 16 + (lane >> 2);
            int col = n0 + wn + nb * 8 + (lane & 3) * 2;
            float b0 = bias[col], b1 = bias[col + 1];
            float v00 = acc[ma][nb][0] + b0, v01 = acc[ma][nb][1] + b1;
            float v10 = acc[ma][nb][2] + b0, v11 = acc[ma][nb][3] + b1;
            if (OUT16) {
                __half* C = (__half*)Cv;
                *(__half2*)(C + (size_t)row * N_ + col)       = __floats2half2_rn(v00, v01);
                *(__half2*)(C + (size_t)(row + 8) * N_ + col) = __floats2half2_rn(v10, v11);
            } else {
                float* C = (float*)Cv;
                *(float2*)(C + (size_t)row * N_ + col)       = make_float2(v00, v01);
                *(float2*)(C + (size_t)(row + 8) * N_ + col) = make_float2(v10, v11);
            }
        }
    }
}

// ───────── per-token attention v3: shuffle softmax + qi-summed P ─────────
// out[h,d] = Σ_g (Σ_qi P[qi,h,g]) · v[g,d]   (qi-sum commutes with P·V)
__global__ __launch_bounds__(256) void attn_kernel(
    const __half* __restrict__ qk, const float* __restrict__ v,
    __half* __restrict__ z)
{
    __shared__ __half2 sq2[QQ][HH][34];
    __shared__ __half2 sk2[HH][34];
    __shared__ float   sv[HH][66];
    __shared__ float   sp_[HH][HH + 1];   // qi-summed probabilities

    const int n   = blockIdx.x;
    const int b   = n >> 11;
    const int sp  = n & 2047;
    const int tid = threadIdx.x;

    // ── load: q 512 uint4, k 128 uint4 (fp16 as-is), v 256 float4 ──
    {
        const uint4* q4 = (const uint4*)(qk + (size_t)n * NQK);
        #pragma unroll
        for (int j = 0; j < 2; j++) {
            int idx = tid + j * 256;
            uint4 u = q4[idx];
            const __half2* h2 = (const __half2*)&u;
            int qi = idx >> 7, rr = (idx >> 3) & 15, cc = (idx & 7) * 4;
            #pragma unroll
            for (int t = 0; t < 4; t++) sq2[qi][rr][cc + t] = h2[t];
        }
        if (tid < 128) {
            uint4 u = q4[512 + tid];
            const __half2* h2 = (const __half2*)&u;
            int rr = tid >> 3, cc = (tid & 7) * 4;
            #pragma unroll
            for (int t = 0; t < 4; t++) sk2[rr][cc + t] = h2[t];
        }
        const float4* v4 = (const float4*)(v + (size_t)n * EE);
        int r = tid >> 4, c4 = (tid & 15) * 4;
        float4 vf = v4[tid];
        sv[r][c4] = vf.x; sv[r][c4+1] = vf.y; sv[r][c4+2] = vf.z; sv[r][c4+3] = vf.w;
    }
    __syncthreads();

    // ── scores + fused softmax + qi accumulation: thread (h,g) ──
    {
        const int h = tid >> 4, g = tid & 15;
        float psum = 0.f;
        #pragma unroll
        for (int qi = 0; qi < QQ; qi++) {
            float s = 0.f;
            #pragma unroll
            for (int dd = 0; dd < 32; dd++) {
                float2 a = __half22float2(sq2[qi][h][dd]);
                float2 c = __half22float2(sk2[g][dd]);
                s += a.x * c.x + a.y * c.y;
            }
            s *= 0.125f;
            float m = s;
            #pragma unroll
            for (int o = 8; o; o >>= 1) m = fmaxf(m, __shfl_xor_sync(~0u, m, o));
            float e = __expf(s - m);
            float sum = e;
            #pragma unroll
            for (int o = 8; o; o >>= 1) sum += __shfl_xor_sync(~0u, sum, o);
            psum += e / sum;
        }
        sp_[h][g] = psum;
    }
    __syncthreads();

    // ── single P·V pass; shuffled fp16 write ──
    const int d  = tid & 63;
    const int hq = tid >> 6;
    #pragma unroll
    for (int j = 0; j < 4; j++) {
        int h = hq * 4 + j;
        const float* pr = sp_[h];
        float o = 0.f;
        #pragma unroll
        for (int g = 0; g < HH; g++) o += pr[g] * sv[g][d];
        int sfin = h * 128 + (sp >> 4);
        int e    = ((sp & 15) << 6) + d;
        z[((size_t)b * SS + sfin) * EE + e] = __float2half_rn(o);
    }
}

// ───────── host ─────────
typedef CUresult (*PFN_encode)(
    CUtensorMap*, CUtensorMapDataType, cuuint32_t, void*,
    const cuuint64_t*, const cuuint64_t*, const cuuint32_t*, const cuuint32_t*,
    CUtensorMapInterleave, CUtensorMapSwizzle, CUtensorMapL2promotion,
    CUtensorMapFloatOOBfill);

static CUtensorMap mk_map16(PFN_encode enc, void* base, u64 rows, u32 boxrows) {
    CUtensorMap m;
    cuuint64_t dims[2]    = {(cuuint64_t)EE, rows};
    cuuint64_t strides[1] = {(cuuint64_t)EE * 2};
    cuuint32_t box[2]     = {64u, boxrows};
    cuuint32_t es[2]      = {1u, 1u};
    enc(&m, CU_TENSOR_MAP_DATA_TYPE_FLOAT16, 2, base, dims, strides, box, es,
        CU_TENSOR_MAP_INTERLEAVE_NONE, CU_TENSOR_MAP_SWIZZLE_128B,
        CU_TENSOR_MAP_L2_PROMOTION_L2_128B, CU_TENSOR_MAP_FLOAT_OOB_FILL_NONE);
    return m;
}

extern "C" void kernel_launch(void* const* d_in, const int* in_sizes, int n_in,
                              void* d_out, int out_size)
{
    const float* x  = (const float*)d_in[0];
    const float* Wq = (const float*)d_in[1];
    const float* bq = (const float*)d_in[2];
    const float* Wk = (const float*)d_in[3];
    const float* bk = (const float*)d_in[4];
    const float* Wv = (const float*)d_in[5];
    const float* bv = (const float*)d_in[6];
    const float* Wo = (const float*)d_in[7];
    const float* bo = (const float*)d_in[8];
    float* out = (float*)d_out;

    float *pv, *pbqkv;
    __half *pqk, *pz, *xh, *wqkv, *wo;
    cudaGetSymbolAddress((void**)&pqk,  g_qk);
    cudaGetSymbolAddress((void**)&pv,   g_v);
    cudaGetSymbolAddress((void**)&pz,   g_z);
    cudaGetSymbolAddress((void**)&pbqkv, g_bqkv);
    cudaGetSymbolAddress((void**)&xh, g_xh);
    cudaGetSymbolAddress((void**)&wqkv, g_wqkv);
    cudaGetSymbolAddress((void**)&wo, g_wo);

    PFN_encode enc = 0;
    cudaDriverEntryPointQueryResult qr;
    cudaGetDriverEntryPoint("cuTensorMapEncodeTiled", (void**)&enc,
                            cudaEnableDefault, &qr);

    CUtensorMap mXh = mk_map16(enc, xh, MM, 128);
    CUtensorMap mZ  = mk_map16(enc, pz, MM, 128);
    CUtensorMap mW  = mk_map16(enc, wqkv, NQKV, 256);
    CUtensorMap mO  = mk_map16(enc, wo, EE, 256);

    cudaFuncSetAttribute(hgemm1<1>, cudaFuncAttributeMaxDynamicSharedMemorySize, GSMEM1);
    cudaFuncSetAttribute(hgemm1<0>, cudaFuncAttributeMaxDynamicSharedMemorySize, GSMEM1);

    dim3 blk(256);
    conv16<<<(MM*EE/4 + 255)/256, blk>>>(x, xh, MM*EE/4);
    conv16<<<(QQ*EE*EE/4 + 255)/256, blk>>>(Wq, wqkv,                QQ*EE*EE/4);
    conv16<<<(EE*EE/4 + 255)/256, blk>>>(Wk, wqkv + (size_t)4096*EE, EE*EE/4);
    conv16<<<(EE*EE/4 + 255)/256, blk>>>(Wv, wqkv + (size_t)5120*EE, EE*EE/4);
    conv16<<<(EE*EE/4 + 255)/256, blk>>>(Wo, wo,                     EE*EE/4);
    bias_concat<<<(NQKV + 255)/256, blk>>>(bq, bk, bv, pbqkv);

    // Q|K: 1-pass, fp16 out (score path — error-attenuated)
    hgemm1<1><<<dim3(NQK/256, MM/128), blk, GSMEM1>>>(
        mXh, mW, pbqkv, pqk, NQK, EE, 0);
    // V: 1-pass, fp32 out (direct path; x-rounding term budgeted)
    hgemm1<0><<<dim3(EE/256, MM/128), blk, GSMEM1>>>(
        mXh, mW, pbqkv + NQK, pv, EE, EE, NQK);

    attn_kernel<<<MM, blk>>>(pqk, pv, pz);

    // O: 1-pass on fp16 z
    hgemm1<0><<<dim3(EE/256, MM/128), blk, GSMEM1>>>(
        mZ, mO, bo, out, EE, EE, 0);
}

// round 14
// speedup vs baseline: 1.8511x; 1.1485x over previous
#include <cuda_runtime.h>
#include <cuda.h>
#include <cuda_fp16.h>

typedef unsigned int u32;
typedef unsigned long long u64;

#define BB 4
#define SS 2048
#define EE 1024
#define HH 16
#define DD 64
#define QQ 4
#define MM (BB*SS)     /* 8192 tokens */
#define NQKV 6144
#define NQK  5120

// ───────── scratch (allocation-free rule: __device__ globals) ─────────
__device__ __half g_qk[(size_t)MM * NQK];      // q|k projection, fp16
__device__ __half g_v [(size_t)MM * EE];       // v projection, fp16 (mma operand)
__device__ __half g_z [(size_t)MM * EE];       // attn output, fp16
__device__ float  g_bqkv[NQKV];

__device__ __half g_xh[(size_t)MM*EE];
__device__ __half g_wqkv[(size_t)NQKV*EE];
__device__ __half g_wo[(size_t)EE*EE];

__device__ __forceinline__ u32 smem_u32(const void* p) {
    u32 a;
    asm("{ .reg .u64 t; cvta.to.shared.u64 t, %1; cvt.u32.u64 %0, t; }"
        : "=r"(a) : "l"(p));
    return a;
}
__device__ __forceinline__ void ldsm4(u32 addr, u32* r) {
    asm volatile("ldmatrix.sync.aligned.m8n8.x4.shared.b16 {%0,%1,%2,%3}, [%4];"
                 : "=r"(r[0]), "=r"(r[1]), "=r"(r[2]), "=r"(r[3]) : "r"(addr));
}
__device__ __forceinline__ void ldsm4t(u32 addr, u32* r) {
    asm volatile("ldmatrix.sync.aligned.m8n8.x4.trans.shared.b16 {%0,%1,%2,%3}, [%4];"
                 : "=r"(r[0]), "=r"(r[1]), "=r"(r[2]), "=r"(r[3]) : "r"(addr));
}
__device__ __forceinline__ void mma16816(float* c, const u32* a, const u32* b) {
    asm volatile(
        "mma.sync.aligned.m16n8k16.row.col.f32.f16.f16.f32 "
        "{%0,%1,%2,%3}, {%4,%5,%6,%7}, {%8,%9}, {%0,%1,%2,%3};"
        : "+f"(c[0]), "+f"(c[1]), "+f"(c[2]), "+f"(c[3])
        : "r"(a[0]), "r"(a[1]), "r"(a[2]), "r"(a[3]), "r"(b[0]), "r"(b[1]));
}
__device__ __forceinline__ void tma2d(u32 saddr, const CUtensorMap* m,
                                      int cx, int cy, u32 mbar) {
    asm volatile(
        "cp.async.bulk.tensor.2d.shared::cta.global.tile.mbarrier::complete_tx::bytes "
        "[%0], [%1, {%2, %3}], [%4];"
        :: "r"(saddr), "l"(m), "r"(cx), "r"(cy), "r"(mbar) : "memory");
}
#define MBAR_INIT(addr, cnt) \
    asm volatile("mbarrier.init.shared.b64 [%0], %1;" :: "r"(addr), "r"(cnt) : "memory")
#define MBAR_EXPECT(addr, bytes) \
    asm volatile("mbarrier.arrive.expect_tx.shared.b64 _, [%0], %1;" \
                 :: "r"(addr), "r"(bytes) : "memory")
__device__ __forceinline__ void mbar_wait(u32 addr, u32 parity) {
    asm volatile(
        "{\n\t.reg .pred P;\n\t"
        "W%=:\n\t"
        "mbarrier.try_wait.parity.acquire.cta.shared::cta.b64 P, [%0], %1, 0x989680;\n\t"
        "@P bra D%=;\n\t"
        "bra W%=;\n\t"
        "D%=:\n\t}"
        :: "r"(addr), "r"(parity) : "memory");
}
#define SWZ(off) ((u32)(off) ^ ((((u32)(off)) >> 3) & 0x70))

// ───────── fp32 → fp16 ─────────
__global__ __launch_bounds__(256) void conv16(
    const float* __restrict__ s, __half* __restrict__ h, int n4)
{
    int i = blockIdx.x * blockDim.x + threadIdx.x;
    if (i >= n4) return;
    float4 v = ((const float4*)s)[i];
    ushort4 ho;
    ho.x = __half_as_ushort(__float2half_rn(v.x));
    ho.y = __half_as_ushort(__float2half_rn(v.y));
    ho.z = __half_as_ushort(__float2half_rn(v.z));
    ho.w = __half_as_ushort(__float2half_rn(v.w));
    ((ushort4*)h)[i] = ho;
}

__global__ __launch_bounds__(256) void bias_concat(
    const float* __restrict__ bq, const float* __restrict__ bk,
    const float* __restrict__ bv, float* __restrict__ dst)
{
    int i = blockIdx.x * blockDim.x + threadIdx.x;
    if (i >= NQKV) return;
    float v;
    if (i < 4096)      v = bq[i];
    else if (i < 5120) v = bk[i - 4096];
    else               v = bv[i - 5120];
    dst[i] = v;
}

// ═════════ 1-PASS fp16 GEMM, 4-stage TMA; OUT16 picks fp16/fp32 output ═════════
#define CHK 64
#define S1_A 0u
#define S1_B 16384u
#define STB1 49152u
#define S1_CTRL (4u*STB1)
#define GSMEM1 (4*49152 + 64)

template<int OUT16>
__global__ __launch_bounds__(256, 1) void hgemm1(
    const __grid_constant__ CUtensorMap tA,
    const __grid_constant__ CUtensorMap tB,
    const float* __restrict__ bias, void* __restrict__ Cv,
    int N_, int K, int ny0)
{
    extern __shared__ __align__(1024) char smem[];
    const u32 sb   = smem_u32(smem);
    const int tid  = threadIdx.x;
    const int wid  = tid >> 5;
    const int lane = tid & 31;
    const int m0   = blockIdx.y * 128;
    const int n0   = blockIdx.x * 256;
    const int wm   = (wid & 1) * 64;
    const int wn   = (wid >> 1) * 64;
    const int nch  = K / CHK;

    float acc[4][8][4];
    #pragma unroll
    for (int i = 0; i < 4; i++)
        #pragma unroll
        for (int j = 0; j < 8; j++)
            #pragma unroll
            for (int t = 0; t < 4; t++) acc[i][j][t] = 0.f;

    if (tid == 0) {
        #pragma unroll
        for (int s = 0; s < 4; s++) MBAR_INIT(sb + S1_CTRL + s * 8, 1);
    }
    __syncthreads();

    auto issue = [&](int c) {
        if (tid == 0) {
            const int st   = c & 3;
            const u32 mbar = sb + S1_CTRL + st * 8;
            const u32 s0   = sb + st * STB1;
            MBAR_EXPECT(mbar, 49152u);
            int kc = c * CHK;
            tma2d(s0 + S1_A, &tA, kc, m0, mbar);
            tma2d(s0 + S1_B, &tB, kc, ny0 + n0, mbar);
        }
    };

    issue(0); issue(1); issue(2); issue(3);

    for (int c = 0; c < nch; c++) {
        const int st = c & 3;
        mbar_wait(sb + S1_CTRL + st * 8, (c >> 2) & 1);
        const u32 s0 = sb + st * STB1;

        #pragma unroll
        for (int ks = 0; ks < 4; ks++) {
            const int k0 = ks * 16;
            u32 a[4][4], b[4][4];
            #pragma unroll
            for (int ma = 0; ma < 4; ma++) {
                int row  = wm + ma * 16 + ((lane >> 3) & 1) * 8 + (lane & 7);
                int colB = (k0 + (lane >> 4) * 8) * 2;
                ldsm4(s0 + S1_A + SWZ(row * 128 + colB), a[ma]);
            }
            #pragma unroll
            for (int j = 0; j < 4; j++) {
                int row  = wn + j * 16 + (lane >> 4) * 8 + (lane & 7);
                int colB = (k0 + ((lane >> 3) & 1) * 8) * 2;
                ldsm4(s0 + S1_B + SWZ(row * 128 + colB), b[j]);
            }
            #pragma unroll
            for (int j = 0; j < 4; j++)
                #pragma unroll
                for (int ma = 0; ma < 4; ma++) {
                    mma16816(acc[ma][j*2+0], a[ma], &b[j][0]);
                    mma16816(acc[ma][j*2+1], a[ma], &b[j][2]);
                }
        }
        __syncthreads();
        if (c + 4 < nch) issue(c + 4);
    }

    #pragma unroll
    for (int ma = 0; ma < 4; ma++) {
        #pragma unroll
        for (int nb = 0; nb < 8; nb++) {
            int row = m0 + wm + ma * 16 + (lane >> 2);
            int col = n0 + wn + nb * 8 + (lane & 3) * 2;
            float b0 = bias[col], b1 = bias[col + 1];
            float v00 = acc[ma][nb][0] + b0, v01 = acc[ma][nb][1] + b1;
            float v10 = acc[ma][nb][2] + b0, v11 = acc[ma][nb][3] + b1;
            if (OUT16) {
                __half* C = (__half*)Cv;
                *(__half2*)(C + (size_t)row * N_ + col)       = __floats2half2_rn(v00, v01);
                *(__half2*)(C + (size_t)(row + 8) * N_ + col) = __floats2half2_rn(v10, v11);
            } else {
                float* C = (float*)Cv;
                *(float2*)(C + (size_t)row * N_ + col)       = make_float2(v00, v01);
                *(float2*)(C + (size_t)(row + 8) * N_ + col) = make_float2(v10, v11);
            }
        }
    }
}

// ───────── attention v4: tensor-core per-token, 1 warp = 1 token ─────────
// Per token: scores = Q(64x64)·K^T via 32 HMMA; softmax via 4-lane shuffles;
// P summed over qi, converted in-register to A-fragments; out = P·V via 8 HMMA.
// smem/token: q 8KB (rows 0-63) + k 2KB (rows 64-79) + v 2KB → 12 KB; 8 tokens/CTA.
#define ATOK 8
#define TOKB 12288
#define ASMEM (ATOK*TOKB)

__global__ __launch_bounds__(256) void attn_kernel(
    const __half* __restrict__ qk, const __half* __restrict__ v,
    __half* __restrict__ z)
{
    extern __shared__ __align__(1024) char smem[];
    const u32 sb   = smem_u32(smem);
    const int tid  = threadIdx.x;
    const int lane = tid & 31;
    const int w    = tid >> 5;
    const int n0   = blockIdx.x * ATOK;

    // ── staging: 8 tokens × (640 qk + 128 v) uint4 = 6144; 24 per thread ──
    #pragma unroll
    for (int i = 0; i < 24; i++) {
        int f   = tid + i * 256;
        int tok = f / 768, rem = f - tok * 768;
        u32 tb = tok * TOKB;
        uint4 val;
        u32 dst;
        if (rem < 640) {               // qk: 80 rows × 8 uint4
            val = ((const uint4*)qk)[(size_t)(n0 + tok) * 640 + rem];
            int row = rem >> 3, c16 = (rem & 7) * 16;
            dst = sb + tb + SWZ(row * 128 + c16);
        } else {                       // v: 16 rows × 8 uint4, region +10240
            int idx = rem - 640;
            val = ((const uint4*)v)[(size_t)(n0 + tok) * 128 + idx];
            int row = idx >> 3, c16 = (idx & 7) * 16;
            dst = sb + tb + 10240 + SWZ(row * 128 + c16);
        }
        *(uint4*)(smem + (dst - sb)) = val;
    }
    __syncthreads();

    // ── per-warp token compute ──
    const int n  = n0 + w;
    const int b  = n >> 11;
    const int sp = n & 2047;
    const u32 tb = sb + w * TOKB;

    // k b-frags (rows 64..79), 4 k-steps
    u32 kb[4][4];
    #pragma unroll
    for (int ks = 0; ks < 4; ks++) {
        int row  = 64 + (lane >> 4) * 8 + (lane & 7);
        int colB = (ks * 16 + ((lane >> 3) & 1) * 8) * 2;
        ldsm4(tb + SWZ(row * 128 + colB), kb[ks]);
    }
    // v b-frags via trans ldsm: region +10240, [g][d] → n8k16 frags
    u32 vb[4][4];
    #pragma unroll
    for (int nb4 = 0; nb4 < 4; nb4++) {
        int row  = lane & 15;                       // g
        int colB = (nb4 * 16 + (lane >> 4) * 8) * 2; // d
        ldsm4t(tb + 10240 + SWZ(row * 128 + colB), vb[nb4]);
    }

    // scores + softmax + qi-summed P
    float psum[8];
    #pragma unroll
    for (int i = 0; i < 8; i++) psum[i] = 0.f;

    #pragma unroll
    for (int qi = 0; qi < QQ; qi++) {
        u32 qa[4][4];
        #pragma unroll
        for (int ks = 0; ks < 4; ks++) {
            int row  = qi * 16 + ((lane >> 3) & 1) * 8 + (lane & 7);
            int colB = (ks * 16 + (lane >> 4) * 8) * 2;
            ldsm4(tb + SWZ(row * 128 + colB), qa[ks]);
        }
        float sc[2][4];
        #pragma unroll
        for (int t = 0; t < 4; t++) { sc[0][t] = 0.f; sc[1][t] = 0.f; }
        #pragma unroll
        for (int ks = 0; ks < 4; ks++) {
            mma16816(sc[0], qa[ks], &kb[ks][0]);
            mma16816(sc[1], qa[ks], &kb[ks][2]);
        }
        // scale
        #pragma unroll
        for (int t = 0; t < 4; t++) { sc[0][t] *= 0.125f; sc[1][t] *= 0.125f; }
        // rows: r0 vals = sc[0][0],sc[0][1],sc[1][0],sc[1][1]; r1 = idx 2,3
        float m0 = fmaxf(fmaxf(sc[0][0], sc[0][1]), fmaxf(sc[1][0], sc[1][1]));
        float m1 = fmaxf(fmaxf(sc[0][2], sc[0][3]), fmaxf(sc[1][2], sc[1][3]));
        #pragma unroll
        for (int o = 1; o <= 2; o <<= 1) {
            m0 = fmaxf(m0, __shfl_xor_sync(~0u, m0, o));
            m1 = fmaxf(m1, __shfl_xor_sync(~0u, m1, o));
        }
        float e00 = __expf(sc[0][0] - m0), e01 = __expf(sc[0][1] - m0);
        float e10 = __expf(sc[1][0] - m0), e11 = __expf(sc[1][1] - m0);
        float f00 = __expf(sc[0][2] - m1), f01 = __expf(sc[0][3] - m1);
        float f10 = __expf(sc[1][2] - m1), f11 = __expf(sc[1][3] - m1);
        float s0 = e00 + e01 + e10 + e11;
        float s1 = f00 + f01 + f10 + f11;
        #pragma unroll
        for (int o = 1; o <= 2; o <<= 1) {
            s0 += __shfl_xor_sync(~0u, s0, o);
            s1 += __shfl_xor_sync(~0u, s1, o);
        }
        float i0 = 1.f / s0, i1 = 1.f / s1;
        psum[0] += e00 * i0; psum[1] += e01 * i0;   // frag0 row r0
        psum[2] += f00 * i1; psum[3] += f01 * i1;   // frag0 row r1
        psum[4] += e10 * i0; psum[5] += e11 * i0;   // frag1 row r0
        psum[6] += f10 * i1; psum[7] += f11 * i1;   // frag1 row r1
    }

    // pack P into A-fragment (c-frag → a-frag identity mapping)
    u32 pa[4];
    {
        __half2 h0 = __floats2half2_rn(psum[0], psum[1]);
        __half2 h1 = __floats2half2_rn(psum[2], psum[3]);
        __half2 h2 = __floats2half2_rn(psum[4], psum[5]);
        __half2 h3 = __floats2half2_rn(psum[6], psum[7]);
        pa[0] = *(u32*)&h0; pa[1] = *(u32*)&h1;
        pa[2] = *(u32*)&h2; pa[3] = *(u32*)&h3;
    }

    // out = P·V : 8 n8 fragments over d=64
    float za[8][4];
    #pragma unroll
    for (int i = 0; i < 8; i++)
        #pragma unroll
        for (int t = 0; t < 4; t++) za[i][t] = 0.f;
    #pragma unroll
    for (int nb4 = 0; nb4 < 4; nb4++) {
        mma16816(za[nb4*2+0], pa, &vb[nb4][0]);
        mma16816(za[nb4*2+1], pa, &vb[nb4][2]);
    }

    // write shuffled fp16: z[b, h*128 + sp/16, (sp%16)*64 + d]
    {
        const int r0 = lane >> 2;          // h rows r0, r0+8
        const int c0 = (lane & 3) * 2;     // d col pair base
        const size_t rowbase = ((size_t)b * SS) * EE;
        const int e0 = ((sp & 15) << 6);
        #pragma unroll
        for (int nb = 0; nb < 8; nb++) {
            int d = nb * 8 + c0;
            __half2 lo = __floats2half2_rn(za[nb][0], za[nb][1]);
            __half2 hi = __floats2half2_rn(za[nb][2], za[nb][3]);
            int s0f = r0 * 128 + (sp >> 4);
            int s1f = (r0 + 8) * 128 + (sp >> 4);
            *(__half2*)(z + rowbase + (size_t)s0f * EE + e0 + d) = lo;
            *(__half2*)(z + rowbase + (size_t)s1f * EE + e0 + d) = hi;
        }
    }
}

// ───────── host ─────────
typedef CUresult (*PFN_encode)(
    CUtensorMap*, CUtensorMapDataType, cuuint32_t, void*,
    const cuuint64_t*, const cuuint64_t*, const cuuint32_t*, const cuuint32_t*,
    CUtensorMapInterleave, CUtensorMapSwizzle, CUtensorMapL2promotion,
    CUtensorMapFloatOOBfill);

static CUtensorMap mk_map16(PFN_encode enc, void* base, u64 rows, u32 boxrows) {
    CUtensorMap m;
    cuuint64_t dims[2]    = {(cuuint64_t)EE, rows};
    cuuint64_t strides[1] = {(cuuint64_t)EE * 2};
    cuuint32_t box[2]     = {64u, boxrows};
    cuuint32_t es[2]      = {1u, 1u};
    enc(&m, CU_TENSOR_MAP_DATA_TYPE_FLOAT16, 2, base, dims, strides, box, es,
        CU_TENSOR_MAP_INTERLEAVE_NONE, CU_TENSOR_MAP_SWIZZLE_128B,
        CU_TENSOR_MAP_L2_PROMOTION_L2_128B, CU_TENSOR_MAP_FLOAT_OOB_FILL_NONE);
    return m;
}

extern "C" void kernel_launch(void* const* d_in, const int* in_sizes, int n_in,
                              void* d_out, int out_size)
{
    const float* x  = (const float*)d_in[0];
    const float* Wq = (const float*)d_in[1];
    const float* bq = (const float*)d_in[2];
    const float* Wk = (const float*)d_in[3];
    const float* bk = (const float*)d_in[4];
    const float* Wv = (const float*)d_in[5];
    const float* bv = (const float*)d_in[6];
    const float* Wo = (const float*)d_in[7];
    const float* bo = (const float*)d_in[8];
    float* out = (float*)d_out;

    float *pbqkv;
    __half *pqk, *pv, *pz, *xh, *wqkv, *wo;
    cudaGetSymbolAddress((void**)&pqk,  g_qk);
    cudaGetSymbolAddress((void**)&pv,   g_v);
    cudaGetSymbolAddress((void**)&pz,   g_z);
    cudaGetSymbolAddress((void**)&pbqkv, g_bqkv);
    cudaGetSymbolAddress((void**)&xh, g_xh);
    cudaGetSymbolAddress((void**)&wqkv, g_wqkv);
    cudaGetSymbolAddress((void**)&wo, g_wo);

    PFN_encode enc = 0;
    cudaDriverEntryPointQueryResult qr;
    cudaGetDriverEntryPoint("cuTensorMapEncodeTiled", (void**)&enc,
                            cudaEnableDefault, &qr);

    CUtensorMap mXh = mk_map16(enc, xh, MM, 128);
    CUtensorMap mZ  = mk_map16(enc, pz, MM, 128);
    CUtensorMap mW  = mk_map16(enc, wqkv, NQKV, 256);
    CUtensorMap mO  = mk_map16(enc, wo, EE, 256);

    cudaFuncSetAttribute(hgemm1<1>, cudaFuncAttributeMaxDynamicSharedMemorySize, GSMEM1);
    cudaFuncSetAttribute(hgemm1<0>, cudaFuncAttributeMaxDynamicSharedMemorySize, GSMEM1);
    cudaFuncSetAttribute(attn_kernel, cudaFuncAttributeMaxDynamicSharedMemorySize, ASMEM);

    dim3 blk(256);
    conv16<<<(MM*EE/4 + 255)/256, blk>>>(x, xh, MM*EE/4);
    conv16<<<(QQ*EE*EE/4 + 255)/256, blk>>>(Wq, wqkv,                QQ*EE*EE/4);
    conv16<<<(EE*EE/4 + 255)/256, blk>>>(Wk, wqkv + (size_t)4096*EE, EE*EE/4);
    conv16<<<(EE*EE/4 + 255)/256, blk>>>(Wv, wqkv + (size_t)5120*EE, EE*EE/4);
    conv16<<<(EE*EE/4 + 255)/256, blk>>>(Wo, wo,                     EE*EE/4);
    bias_concat<<<(NQKV + 255)/256, blk>>>(bq, bk, bv, pbqkv);

    // Q|K: 1-pass, fp16 out
    hgemm1<1><<<dim3(NQK/256, MM/128), blk, GSMEM1>>>(
        mXh, mW, pbqkv, pqk, NQK, EE, 0);
    // V: 1-pass, fp16 out (mma operand for attn)
    hgemm1<1><<<dim3(EE/256, MM/128), blk, GSMEM1>>>(
        mXh, mW, pbqkv + NQK, pv, EE, EE, NQK);

    // tensor-core attention: 8 tokens per CTA
    attn_kernel<<<MM/ATOK, blk, ASMEM>>>(pqk, pv, pz);

    // O: 1-pass on fp16 z
    hgemm1<0><<<dim3(EE/256, MM/128), blk, GSMEM1>>>(
        mZ, mO, bo, out, EE, EE, 0);
}

// round 15
// speedup vs baseline: 1.9115x; 1.0326x over previous
#include <cuda_runtime.h>
#include <cuda.h>
#include <cuda_fp16.h>

typedef unsigned int u32;
typedef unsigned long long u64;

#define BB 4
#define SS 2048
#define EE 1024
#define HH 16
#define DD 64
#define QQ 4
#define MM (BB*SS)     /* 8192 tokens */
#define NQKV 6144
#define NQK  5120

// ───────── scratch (allocation-free rule: __device__ globals) ─────────
__device__ __half g_qkv[(size_t)MM * NQKV];    // fused q|k|v projection, fp16
__device__ __half g_z  [(size_t)MM * EE];      // attn output, fp16
__device__ float  g_bqkv[NQKV];

__device__ __half g_xh[(size_t)MM*EE];
__device__ __half g_wqkv[(size_t)NQKV*EE];
__device__ __half g_wo[(size_t)EE*EE];

__device__ __forceinline__ u32 smem_u32(const void* p) {
    u32 a;
    asm("{ .reg .u64 t; cvta.to.shared.u64 t, %1; cvt.u32.u64 %0, t; }"
        : "=r"(a) : "l"(p));
    return a;
}
__device__ __forceinline__ void ldsm4(u32 addr, u32* r) {
    asm volatile("ldmatrix.sync.aligned.m8n8.x4.shared.b16 {%0,%1,%2,%3}, [%4];"
                 : "=r"(r[0]), "=r"(r[1]), "=r"(r[2]), "=r"(r[3]) : "r"(addr));
}
__device__ __forceinline__ void ldsm4t(u32 addr, u32* r) {
    asm volatile("ldmatrix.sync.aligned.m8n8.x4.trans.shared.b16 {%0,%1,%2,%3}, [%4];"
                 : "=r"(r[0]), "=r"(r[1]), "=r"(r[2]), "=r"(r[3]) : "r"(addr));
}
__device__ __forceinline__ void mma16816(float* c, const u32* a, const u32* b) {
    asm volatile(
        "mma.sync.aligned.m16n8k16.row.col.f32.f16.f16.f32 "
        "{%0,%1,%2,%3}, {%4,%5,%6,%7}, {%8,%9}, {%0,%1,%2,%3};"
        : "+f"(c[0]), "+f"(c[1]), "+f"(c[2]), "+f"(c[3])
        : "r"(a[0]), "r"(a[1]), "r"(a[2]), "r"(a[3]), "r"(b[0]), "r"(b[1]));
}
__device__ __forceinline__ void tma2d(u32 saddr, const CUtensorMap* m,
                                      int cx, int cy, u32 mbar) {
    asm volatile(
        "cp.async.bulk.tensor.2d.shared::cta.global.tile.mbarrier::complete_tx::bytes "
        "[%0], [%1, {%2, %3}], [%4];"
        :: "r"(saddr), "l"(m), "r"(cx), "r"(cy), "r"(mbar) : "memory");
}
#define MBAR_INIT(addr, cnt) \
    asm volatile("mbarrier.init.shared.b64 [%0], %1;" :: "r"(addr), "r"(cnt) : "memory")
#define MBAR_EXPECT(addr, bytes) \
    asm volatile("mbarrier.arrive.expect_tx.shared.b64 _, [%0], %1;" \
                 :: "r"(addr), "r"(bytes) : "memory")
__device__ __forceinline__ void mbar_wait(u32 addr, u32 parity) {
    asm volatile(
        "{\n\t.reg .pred P;\n\t"
        "W%=:\n\t"
        "mbarrier.try_wait.parity.acquire.cta.shared::cta.b64 P, [%0], %1, 0x989680;\n\t"
        "@P bra D%=;\n\t"
        "bra W%=;\n\t"
        "D%=:\n\t}"
        :: "r"(addr), "r"(parity) : "memory");
}
#define SWZ(off) ((u32)(off) ^ ((((u32)(off)) >> 3) & 0x70))

// ───────── fused fp32→fp16 conversion of x, Wq, Wk, Wv, Wo ─────────
#define C_X  2097152
#define C_WQ (C_X + 1048576)
#define C_WK (C_WQ + 262144)
#define C_WV (C_WK + 262144)
#define C_WO (C_WV + 262144)

__global__ __launch_bounds__(256) void conv_all(
    const float* __restrict__ x,  const float* __restrict__ Wq,
    const float* __restrict__ Wk, const float* __restrict__ Wv,
    const float* __restrict__ Wo,
    __half* __restrict__ xh, __half* __restrict__ wqkv, __half* __restrict__ wo)
{
    int i = blockIdx.x * blockDim.x + threadIdx.x;
    const float* s; __half* d; int off;
    if (i < C_X)       { s = x;  d = xh;                           off = i; }
    else if (i < C_WQ) { s = Wq; d = wqkv;                         off = i - C_X; }
    else if (i < C_WK) { s = Wk; d = wqkv + (size_t)4096*EE;       off = i - C_WQ; }
    else if (i < C_WV) { s = Wv; d = wqkv + (size_t)5120*EE;       off = i - C_WK; }
    else               { s = Wo; d = wo;                           off = i - C_WV; }
    float4 v = ((const float4*)s)[off];
    ushort4 ho;
    ho.x = __half_as_ushort(__float2half_rn(v.x));
    ho.y = __half_as_ushort(__float2half_rn(v.y));
    ho.z = __half_as_ushort(__float2half_rn(v.z));
    ho.w = __half_as_ushort(__float2half_rn(v.w));
    ((ushort4*)d)[off] = ho;
}

__global__ __launch_bounds__(256) void bias_concat(
    const float* __restrict__ bq, const float* __restrict__ bk,
    const float* __restrict__ bv, float* __restrict__ dst)
{
    int i = blockIdx.x * blockDim.x + threadIdx.x;
    if (i >= NQKV) return;
    float v;
    if (i < 4096)      v = bq[i];
    else if (i < 5120) v = bk[i - 4096];
    else               v = bv[i - 5120];
    dst[i] = v;
}

// ═════════ 1-PASS fp16 GEMM, 4-stage TMA; OUT16 picks fp16/fp32 output ═════════
#define CHK 64
#define S1_A 0u
#define S1_B 16384u
#define STB1 49152u
#define S1_CTRL (4u*STB1)
#define GSMEM1 (4*49152 + 64)

template<int OUT16>
__global__ __launch_bounds__(256, 1) void hgemm1(
    const __grid_constant__ CUtensorMap tA,
    const __grid_constant__ CUtensorMap tB,
    const float* __restrict__ bias, void* __restrict__ Cv,
    int N_, int K, int ny0)
{
    extern __shared__ __align__(1024) char smem[];
    const u32 sb   = smem_u32(smem);
    const int tid  = threadIdx.x;
    const int wid  = tid >> 5;
    const int lane = tid & 31;
    const int m0   = blockIdx.y * 128;
    const int n0   = blockIdx.x * 256;
    const int wm   = (wid & 1) * 64;
    const int wn   = (wid >> 1) * 64;
    const int nch  = K / CHK;

    float acc[4][8][4];
    #pragma unroll
    for (int i = 0; i < 4; i++)
        #pragma unroll
        for (int j = 0; j < 8; j++)
            #pragma unroll
            for (int t = 0; t < 4; t++) acc[i][j][t] = 0.f;

    if (tid == 0) {
        #pragma unroll
        for (int s = 0; s < 4; s++) MBAR_INIT(sb + S1_CTRL + s * 8, 1);
    }
    __syncthreads();

    auto issue = [&](int c) {
        if (tid == 0) {
            const int st   = c & 3;
            const u32 mbar = sb + S1_CTRL + st * 8;
            const u32 s0   = sb + st * STB1;
            MBAR_EXPECT(mbar, 49152u);
            int kc = c * CHK;
            tma2d(s0 + S1_A, &tA, kc, m0, mbar);
            tma2d(s0 + S1_B, &tB, kc, ny0 + n0, mbar);
        }
    };

    issue(0); issue(1); issue(2); issue(3);

    for (int c = 0; c < nch; c++) {
        const int st = c & 3;
        mbar_wait(sb + S1_CTRL + st * 8, (c >> 2) & 1);
        const u32 s0 = sb + st * STB1;

        #pragma unroll
        for (int ks = 0; ks < 4; ks++) {
            const int k0 = ks * 16;
            u32 a[4][4], b[4][4];
            #pragma unroll
            for (int ma = 0; ma < 4; ma++) {
                int row  = wm + ma * 16 + ((lane >> 3) & 1) * 8 + (lane & 7);
                int colB = (k0 + (lane >> 4) * 8) * 2;
                ldsm4(s0 + S1_A + SWZ(row * 128 + colB), a[ma]);
            }
            #pragma unroll
            for (int j = 0; j < 4; j++) {
                int row  = wn + j * 16 + (lane >> 4) * 8 + (lane & 7);
                int colB = (k0 + ((lane >> 3) & 1) * 8) * 2;
                ldsm4(s0 + S1_B + SWZ(row * 128 + colB), b[j]);
            }
            #pragma unroll
            for (int j = 0; j < 4; j++)
                #pragma unroll
                for (int ma = 0; ma < 4; ma++) {
                    mma16816(acc[ma][j*2+0], a[ma], &b[j][0]);
                    mma16816(acc[ma][j*2+1], a[ma], &b[j][2]);
                }
        }
        __syncthreads();
        if (c + 4 < nch) issue(c + 4);
    }

    #pragma unroll
    for (int ma = 0; ma < 4; ma++) {
        #pragma unroll
        for (int nb = 0; nb < 8; nb++) {
            int row = m0 + wm + ma * 16 + (lane >> 2);
            int col = n0 + wn + nb * 8 + (lane & 3) * 2;
            float b0 = bias[col], b1 = bias[col + 1];
            float v00 = acc[ma][nb][0] + b0, v01 = acc[ma][nb][1] + b1;
            float v10 = acc[ma][nb][2] + b0, v11 = acc[ma][nb][3] + b1;
            if (OUT16) {
                __half* C = (__half*)Cv;
                *(__half2*)(C + (size_t)row * N_ + col)       = __floats2half2_rn(v00, v01);
                *(__half2*)(C + (size_t)(row + 8) * N_ + col) = __floats2half2_rn(v10, v11);
            } else {
                float* C = (float*)Cv;
                *(float2*)(C + (size_t)row * N_ + col)       = make_float2(v00, v01);
                *(float2*)(C + (size_t)(row + 8) * N_ + col) = make_float2(v10, v11);
            }
        }
    }
}

// ───────── attention v5: per-warp token, warp-private staging, NO CTA barrier ─────
// qkv row per token is contiguous (768 uint4 = 12 KB): q rows 0-63, k rows 64-79,
// v rows 80-95 of the token's smem block. Each warp stages its own token, syncwarp,
// then HMMA scores → shuffle softmax → qi-summed P → HMMA P·V.
#define ATOK 8
#define TOKB 12288
#define ASMEM (ATOK*TOKB)

__global__ __launch_bounds__(256) void attn_kernel(
    const __half* __restrict__ qkv, __half* __restrict__ z)
{
    extern __shared__ __align__(1024) char smem[];
    const u32 sb   = smem_u32(smem);
    const int tid  = threadIdx.x;
    const int lane = tid & 31;
    const int w    = tid >> 5;
    const int n    = blockIdx.x * ATOK + w;
    const int b    = n >> 11;
    const int sp   = n & 2047;
    const u32 tb   = sb + w * TOKB;

    // ── warp-private staging: 768 uint4 (full q|k|v row), 24 per lane ──
    {
        const uint4* src = (const uint4*)qkv + (size_t)n * 768;
        #pragma unroll
        for (int i = 0; i < 24; i++) {
            int idx = lane + i * 32;
            uint4 val = src[idx];
            *(uint4*)(smem + (u32)w * TOKB + SWZ(idx * 16)) = val;
        }
    }
    __syncwarp();

    // k b-frags (rows 64..79)
    u32 kb[4][4];
    #pragma unroll
    for (int ks = 0; ks < 4; ks++) {
        int row  = 64 + (lane >> 4) * 8 + (lane & 7);
        int colB = (ks * 16 + ((lane >> 3) & 1) * 8) * 2;
        ldsm4(tb + SWZ(row * 128 + colB), kb[ks]);
    }
    // v b-frags via trans ldsm (rows 80..95 → region +10240)
    u32 vb[4][4];
    #pragma unroll
    for (int nb4 = 0; nb4 < 4; nb4++) {
        int row  = lane & 15;
        int colB = (nb4 * 16 + (lane >> 4) * 8) * 2;
        ldsm4t(tb + 10240 + SWZ(row * 128 + colB), vb[nb4]);
    }

    float psum[8];
    #pragma unroll
    for (int i = 0; i < 8; i++) psum[i] = 0.f;

    #pragma unroll
    for (int qi = 0; qi < QQ; qi++) {
        u32 qa[4][4];
        #pragma unroll
        for (int ks = 0; ks < 4; ks++) {
            int row  = qi * 16 + ((lane >> 3) & 1) * 8 + (lane & 7);
            int colB = (ks * 16 + (lane >> 4) * 8) * 2;
            ldsm4(tb + SWZ(row * 128 + colB), qa[ks]);
        }
        float sc[2][4];
        #pragma unroll
        for (int t = 0; t < 4; t++) { sc[0][t] = 0.f; sc[1][t] = 0.f; }
        #pragma unroll
        for (int ks = 0; ks < 4; ks++) {
            mma16816(sc[0], qa[ks], &kb[ks][0]);
            mma16816(sc[1], qa[ks], &kb[ks][2]);
        }
        #pragma unroll
        for (int t = 0; t < 4; t++) { sc[0][t] *= 0.125f; sc[1][t] *= 0.125f; }
        float m0 = fmaxf(fmaxf(sc[0][0], sc[0][1]), fmaxf(sc[1][0], sc[1][1]));
        float m1 = fmaxf(fmaxf(sc[0][2], sc[0][3]), fmaxf(sc[1][2], sc[1][3]));
        #pragma unroll
        for (int o = 1; o <= 2; o <<= 1) {
            m0 = fmaxf(m0, __shfl_xor_sync(~0u, m0, o));
            m1 = fmaxf(m1, __shfl_xor_sync(~0u, m1, o));
        }
        float e00 = __expf(sc[0][0] - m0), e01 = __expf(sc[0][1] - m0);
        float e10 = __expf(sc[1][0] - m0), e11 = __expf(sc[1][1] - m0);
        float f00 = __expf(sc[0][2] - m1), f01 = __expf(sc[0][3] - m1);
        float f10 = __expf(sc[1][2] - m1), f11 = __expf(sc[1][3] - m1);
        float s0 = e00 + e01 + e10 + e11;
        float s1 = f00 + f01 + f10 + f11;
        #pragma unroll
        for (int o = 1; o <= 2; o <<= 1) {
            s0 += __shfl_xor_sync(~0u, s0, o);
            s1 += __shfl_xor_sync(~0u, s1, o);
        }
        float i0 = 1.f / s0, i1 = 1.f / s1;
        psum[0] += e00 * i0; psum[1] += e01 * i0;
        psum[2] += f00 * i1; psum[3] += f01 * i1;
        psum[4] += e10 * i0; psum[5] += e11 * i0;
        psum[6] += f10 * i1; psum[7] += f11 * i1;
    }

    u32 pa[4];
    {
        __half2 h0 = __floats2half2_rn(psum[0], psum[1]);
        __half2 h1 = __floats2half2_rn(psum[2], psum[3]);
        __half2 h2 = __floats2half2_rn(psum[4], psum[5]);
        __half2 h3 = __floats2half2_rn(psum[6], psum[7]);
        pa[0] = *(u32*)&h0; pa[1] = *(u32*)&h1;
        pa[2] = *(u32*)&h2; pa[3] = *(u32*)&h3;
    }

    float za[8][4];
    #pragma unroll
    for (int i = 0; i < 8; i++)
        #pragma unroll
        for (int t = 0; t < 4; t++) za[i][t] = 0.f;
    #pragma unroll
    for (int nb4 = 0; nb4 < 4; nb4++) {
        mma16816(za[nb4*2+0], pa, &vb[nb4][0]);
        mma16816(za[nb4*2+1], pa, &vb[nb4][2]);
    }

    {
        const int r0 = lane >> 2;
        const int c0 = (lane & 3) * 2;
        const size_t rowbase = ((size_t)b * SS) * EE;
        const int e0 = ((sp & 15) << 6);
        #pragma unroll
        for (int nb = 0; nb < 8; nb++) {
            int d = nb * 8 + c0;
            __half2 lo = __floats2half2_rn(za[nb][0], za[nb][1]);
            __half2 hi = __floats2half2_rn(za[nb][2], za[nb][3]);
            int s0f = r0 * 128 + (sp >> 4);
            int s1f = (r0 + 8) * 128 + (sp >> 4);
            *(__half2*)(z + rowbase + (size_t)s0f * EE + e0 + d) = lo;
            *(__half2*)(z + rowbase + (size_t)s1f * EE + e0 + d) = hi;
        }
    }
}

// ───────── host ─────────
typedef CUresult (*PFN_encode)(
    CUtensorMap*, CUtensorMapDataType, cuuint32_t, void*,
    const cuuint64_t*, const cuuint64_t*, const cuuint32_t*, const cuuint32_t*,
    CUtensorMapInterleave, CUtensorMapSwizzle, CUtensorMapL2promotion,
    CUtensorMapFloatOOBfill);

static CUtensorMap mk_map16(PFN_encode enc, void* base, u64 rows, u32 boxrows) {
    CUtensorMap m;
    cuuint64_t dims[2]    = {(cuuint64_t)EE, rows};
    cuuint64_t strides[1] = {(cuuint64_t)EE * 2};
    cuuint32_t box[2]     = {64u, boxrows};
    cuuint32_t es[2]      = {1u, 1u};
    enc(&m, CU_TENSOR_MAP_DATA_TYPE_FLOAT16, 2, base, dims, strides, box, es,
        CU_TENSOR_MAP_INTERLEAVE_NONE, CU_TENSOR_MAP_SWIZZLE_128B,
        CU_TENSOR_MAP_L2_PROMOTION_L2_128B, CU_TENSOR_MAP_FLOAT_OOB_FILL_NONE);
    return m;
}

extern "C" void kernel_launch(void* const* d_in, const int* in_sizes, int n_in,
                              void* d_out, int out_size)
{
    const float* x  = (const float*)d_in[0];
    const float* Wq = (const float*)d_in[1];
    const float* bq = (const float*)d_in[2];
    const float* Wk = (const float*)d_in[3];
    const float* bk = (const float*)d_in[4];
    const float* Wv = (const float*)d_in[5];
    const float* bv = (const float*)d_in[6];
    const float* Wo = (const float*)d_in[7];
    const float* bo = (const float*)d_in[8];
    float* out = (float*)d_out;

    float *pbqkv;
    __half *pqkv, *pz, *xh, *wqkv, *wo;
    cudaGetSymbolAddress((void**)&pqkv, g_qkv);
    cudaGetSymbolAddress((void**)&pz,   g_z);
    cudaGetSymbolAddress((void**)&pbqkv, g_bqkv);
    cudaGetSymbolAddress((void**)&xh, g_xh);
    cudaGetSymbolAddress((void**)&wqkv, g_wqkv);
    cudaGetSymbolAddress((void**)&wo, g_wo);

    PFN_encode enc = 0;
    cudaDriverEntryPointQueryResult qr;
    cudaGetDriverEntryPoint("cuTensorMapEncodeTiled", (void**)&enc,
                            cudaEnableDefault, &qr);

    CUtensorMap mXh = mk_map16(enc, xh, MM, 128);
    CUtensorMap mZ  = mk_map16(enc, pz, MM, 128);
    CUtensorMap mW  = mk_map16(enc, wqkv, NQKV, 256);
    CUtensorMap mO  = mk_map16(enc, wo, EE, 256);

    cudaFuncSetAttribute(hgemm1<1>, cudaFuncAttributeMaxDynamicSharedMemorySize, GSMEM1);
    cudaFuncSetAttribute(hgemm1<0>, cudaFuncAttributeMaxDynamicSharedMemorySize, GSMEM1);
    cudaFuncSetAttribute(attn_kernel, cudaFuncAttributeMaxDynamicSharedMemorySize, ASMEM);

    dim3 blk(256);
    conv_all<<<C_WO/256, blk>>>(x, Wq, Wk, Wv, Wo, xh, wqkv, wo);
    bias_concat<<<(NQKV + 255)/256, blk>>>(bq, bk, bv, pbqkv);

    // fused Q|K|V projection: one GEMM, N=6144, all fp16 out
    hgemm1<1><<<dim3(NQKV/256, MM/128), blk, GSMEM1>>>(
        mXh, mW, pbqkv, pqkv, NQKV, EE, 0);

    // tensor-core attention, warp-private tokens
    attn_kernel<<<MM/ATOK, blk, ASMEM>>>(pqkv, pz);

    // O: 1-pass on fp16 z
    hgemm1<0><<<dim3(EE/256, MM/128), blk, GSMEM1>>>(
        mZ, mO, bo, out, EE, EE, 0);
}